// round 11
// baseline (speedup 1.0000x reference)
#include <cuda_runtime.h>
#include <cuda_fp16.h>
#include <math.h>
#include <stdint.h>

#define Bb 4
#define Ss 1024
#define Ee 1024
#define Hh 16
#define HD 64
#define BH (Bb*Hh)

// ---------------- scratch (no allocs allowed) ----------------
__device__ float g_attn[67108864];               // fallback if attn not in d_out
__device__ __half g_aq[Bb * Ss * Ee];
__device__ __half g_ak[Bb * Ss * Ee];
__device__ __half g_av[Bb * Ss * Ee];
__device__ __half g_wq[Ee * Ee];
__device__ __half g_wk[Ee * Ee];
__device__ __half g_wv[Ee * Ee];
__device__ __half g_wo[Ee * Ee];
__device__ __half g_q16[BH * Ss * HD];
__device__ __half g_k16[BH * Ss * HD];
__device__ __half g_v16[BH * Ss * HD];
__device__ __half g_c16[Bb * Ss * Ee];

// ==================== helpers ====================
static __device__ __forceinline__ uint32_t s2u(const void* p) {
    uint32_t a;
    asm("{ .reg .u64 t; cvta.to.shared.u64 t, %1; cvt.u32.u64 %0, t; }" : "=r"(a) : "l"(p));
    return a;
}

static __device__ __forceinline__ void cp16(uint32_t saddr, const void* g) {
    asm volatile("cp.async.cg.shared.global [%0], [%1], 16;" :: "r"(saddr), "l"(g) : "memory");
}

static __device__ __forceinline__ void mma_f16(float c[4], const uint32_t a[4], const uint32_t b[2]) {
    asm volatile(
        "mma.sync.aligned.m16n8k16.row.col.f32.f16.f16.f32 "
        "{%0,%1,%2,%3}, {%4,%5,%6,%7}, {%8,%9}, {%0,%1,%2,%3};"
        : "+f"(c[0]), "+f"(c[1]), "+f"(c[2]), "+f"(c[3])
        : "r"(a[0]), "r"(a[1]), "r"(a[2]), "r"(a[3]), "r"(b[0]), "r"(b[1]));
}

static __device__ __forceinline__ void ldmx2t(uint32_t& r0, uint32_t& r1, uint32_t addr) {
    asm volatile("ldmatrix.sync.aligned.m8n8.x2.trans.shared.b16 {%0,%1}, [%2];"
                 : "=r"(r0), "=r"(r1) : "r"(addr));
}

static __device__ __forceinline__ uint32_t packh(float x, float y) {
    __half2 h = __floats2half2_rn(x, y);
    return *reinterpret_cast<uint32_t*>(&h);
}

// ==================== batched convert: fp32 -> fp16 (8 floats/thread) ====================
struct ConvArgs {
    const float4 *s0, *s1, *s2, *s3;
    __half *d0, *d1, *d2, *d3;
};

__global__ void __launch_bounds__(256) conv_batch(ConvArgs a, int n8)
{
    const float4* src; __half* dst;
    switch (blockIdx.y) {
        case 0:  src = a.s0; dst = a.d0; break;
        case 1:  src = a.s1; dst = a.d1; break;
        case 2:  src = a.s2; dst = a.d2; break;
        default: src = a.s3; dst = a.d3; break;
    }
    int i = blockIdx.x * 256 + threadIdx.x;
    if (i >= n8) return;
    float4 v0 = src[2 * (size_t)i];
    float4 v1 = src[2 * (size_t)i + 1];
    uint4 r;
    r.x = packh(v0.x, v0.y); r.y = packh(v0.z, v0.w);
    r.z = packh(v1.x, v1.y); r.w = packh(v1.z, v1.w);
    *reinterpret_cast<uint4*>(dst + 8 * (size_t)i) = r;
}

// ==================== zero tail of attn (cols >= nchunk*128) ====================
__global__ void __launch_bounds__(256) zero_tail(float* __restrict__ attn)
{
    const int qt = blockIdx.x;
    const int bh = blockIdx.y;
    const int q0 = qt << 5;
    const int nchunk = (q0 + 159) >> 7;
    const int c0 = nchunk * 128;
    const int ncols = Ss - c0;
    if (ncols <= 0) return;
    const int nc4 = ncols >> 2;
    const float4 z = make_float4(0.f, 0.f, 0.f, 0.f);
    const int total4 = 32 * nc4;
    for (int i = threadIdx.x; i < total4; i += 256) {
        int r = i / nc4;
        int c = (i - r * nc4) << 2;
        __stcs(reinterpret_cast<float4*>(
                   attn + ((size_t)bh * Ss + q0 + r) * Ss + c0 + c), z);
    }
}

// ==================== fp16 mma GEMM body (R6 scalar-LDS version) ====================
#define ARR_B   10240
#define STAGE_B 20480
#define GEMM_SMEM (4 * STAGE_B)

template<int MODE>
static __device__ __forceinline__ void gemm_body(
    const __half* __restrict__ A, const __half* __restrict__ W,
    const float* __restrict__ bias, float* __restrict__ C, __half* __restrict__ C16)
{
    extern __shared__ __align__(128) char smem[];
    const uint32_t sb = s2u(smem);
    const int tid = threadIdx.x;
    const int lane = tid & 31, wid = tid >> 5;
    const int wm = wid & 3, wn = wid >> 2;
    const int bm = blockIdx.y << 7, bn = blockIdx.x << 7;
    const int K = 1024;

    const int c0 = tid << 1;
    const int lrow = c0 >> 2, lcc = c0 & 3;
    const __half* pA = A + (size_t)(bm + lrow) * K + lcc * 8;
    const __half* pW = W + (size_t)(bn + lrow) * K + lcc * 8;
    const uint32_t so = (uint32_t)(lrow * 80 + lcc * 16);

#define LOAD_STAGE(s, kt) do {                                          \
        uint32_t b_ = sb + (uint32_t)(s) * STAGE_B + so;                \
        const int ko_ = (kt) * 32;                                      \
        cp16(b_,              pA + ko_);                                \
        cp16(b_ + 16,         pA + ko_ + 8);                            \
        cp16(b_ + ARR_B,      pW + ko_);                                \
        cp16(b_ + ARR_B + 16, pW + ko_ + 8);                            \
        asm volatile("cp.async.commit_group;" ::: "memory");            \
    } while (0)

    float acc[2][8][4];
#pragma unroll
    for (int a = 0; a < 2; a++)
#pragma unroll
        for (int b = 0; b < 8; b++)
#pragma unroll
            for (int c = 0; c < 4; c++) acc[a][b][c] = 0.f;

    LOAD_STAGE(0, 0);
    LOAD_STAGE(1, 1);

    const int fr = lane >> 2, fq = lane & 3;

    for (int kt = 0; kt < 32; kt++) {
        const int s = kt & 3;
        if (kt <= 29) LOAD_STAGE((kt + 2) & 3, kt + 2);
        if (kt < 30)       asm volatile("cp.async.wait_group 2;" ::: "memory");
        else if (kt == 30) asm volatile("cp.async.wait_group 1;" ::: "memory");
        else               asm volatile("cp.async.wait_group 0;" ::: "memory");
        __syncthreads();

        const uint32_t* SA = (const uint32_t*)(smem + (size_t)s * STAGE_B);
        const uint32_t* SW = SA + ARR_B / 4;

#pragma unroll
        for (int ks = 0; ks < 2; ks++) {
            const int w0 = ks * 8 + fq;
            uint32_t ah[2][4];
#pragma unroll
            for (int mt = 0; mt < 2; mt++) {
                int ra = wm * 32 + mt * 16 + fr;
                ah[mt][0] = SA[ra * 20 + w0];
                ah[mt][1] = SA[(ra + 8) * 20 + w0];
                ah[mt][2] = SA[ra * 20 + w0 + 4];
                ah[mt][3] = SA[(ra + 8) * 20 + w0 + 4];
            }
            uint32_t bf[8][2];
#pragma unroll
            for (int nt = 0; nt < 8; nt++) {
                int rb = wn * 64 + nt * 8 + fr;
                bf[nt][0] = SW[rb * 20 + w0];
                bf[nt][1] = SW[rb * 20 + w0 + 4];
            }
#pragma unroll
            for (int mt = 0; mt < 2; mt++)
#pragma unroll
                for (int nt = 0; nt < 8; nt++)
                    mma_f16(acc[mt][nt], ah[mt], bf[nt]);
        }
    }

    // epilogue
    const int q2 = (lane & 3) * 2;
#pragma unroll
    for (int mt = 0; mt < 2; mt++) {
#pragma unroll
        for (int i = 0; i < 2; i++) {
            int m = bm + wm * 32 + mt * 16 + fr + i * 8;
#pragma unroll
            for (int nt = 0; nt < 8; nt++) {
                int n = bn + wn * 64 + nt * 8 + q2;
                float vx = acc[mt][nt][i * 2 + 0] + bias[n];
                float vy = acc[mt][nt][i * 2 + 1] + bias[n + 1];
                if (MODE) {
                    size_t idx = ((((size_t)(m >> 10) * Hh + (n >> 6)) * Ss
                                   + (size_t)(m & 1023)) << 6) + (n & 63);
                    *reinterpret_cast<uint32_t*>(C16 + idx) = packh(vx, vy);
                } else {
                    float2 v = make_float2(vx, vy);
                    *reinterpret_cast<float2*>(C + (size_t)m * Ee + n) = v;
                }
            }
        }
    }
#undef LOAD_STAGE
}

struct QKVArgs {
    const __half *A0, *A1, *A2;
    const __half *W0, *W1, *W2;
    const float  *b0, *b1, *b2;
    __half *O0, *O1, *O2;
};

__global__ void __launch_bounds__(256) gemm_qkv(QKVArgs a)
{
    const __half *A, *W; const float* b; __half* O;
    switch (blockIdx.z) {
        case 0:  A = a.A0; W = a.W0; b = a.b0; O = a.O0; break;
        case 1:  A = a.A1; W = a.W1; b = a.b1; O = a.O1; break;
        default: A = a.A2; W = a.W2; b = a.b2; O = a.O2; break;
    }
    gemm_body<1>(A, W, b, nullptr, O);
}

__global__ void __launch_bounds__(256) gemm_o(
    const __half* __restrict__ A, const __half* __restrict__ W,
    const float* __restrict__ bias, float* __restrict__ C)
{
    gemm_body<0>(A, W, bias, C, nullptr);
}

// ==================== fused attention (R10 winner minus tail-zero writes) ====================
#define S_STRIDE 1036
#define ROW_B    4144
#define SM_Q_OFF 132608
#define SM_K_OFF 137216
#define KV_BUF   18432
#define FUSED_SMEM (SM_K_OFF + 2 * KV_BUF)

__global__ void __launch_bounds__(256, 1) fused_attn(
    const __half* __restrict__ q16, const __half* __restrict__ k16,
    const __half* __restrict__ v16,
    float* __restrict__ attn, __half* __restrict__ c16)
{
    extern __shared__ __align__(16) char sm[];
    float* S = (float*)sm;
    const uint32_t* Qh = (const uint32_t*)(sm + SM_Q_OFF);
    const uint32_t sQu = s2u(sm + SM_Q_OFF);
    const uint32_t sKu = s2u(sm + SM_K_OFF);

    const int tid = threadIdx.x, lane = tid & 31, wid = tid >> 5;
    const int fr = lane >> 2, fq = lane & 3;
    const int bh = blockIdx.y;
    const int qt = (int)gridDim.x - 1 - (int)blockIdx.x;   // heavy tiles first
    const int q0 = qt << 5;
    const int nchunk = (q0 + 159) >> 7;
    const size_t kvbase = (size_t)bh * Ss * HD;
    const int lseg = tid & 7, lr8 = tid >> 3;

    // ---- stage Q (32x64) + K chunk 0 into buf0 ----
    {
        cp16(sQu + lr8 * 144 + lseg * 16, q16 + kvbase + (size_t)(q0 + lr8) * 64 + lseg * 8);
#pragma unroll
        for (int p = 0; p < 4; p++) {
            int r2 = lr8 + p * 32;
            cp16(sKu + r2 * 144 + lseg * 16, k16 + kvbase + (size_t)r2 * 64 + lseg * 8);
        }
        asm volatile("cp.async.commit_group;" ::: "memory");
    }

    // ---- phase 1: scores (K double-buffered) ----
    const int wm = wid & 1, wnq = wid >> 1;      // 2m x 4n(32)
    for (int c = 0; c < nchunk; c++) {
        if (c + 1 < nchunk) {
            uint32_t dst = sKu + ((c + 1) & 1) * KV_BUF;
#pragma unroll
            for (int p = 0; p < 4; p++) {
                int r2 = lr8 + p * 32;
                cp16(dst + r2 * 144 + lseg * 16,
                     k16 + kvbase + ((size_t)(c + 1) * 128 + r2) * 64 + lseg * 8);
            }
            asm volatile("cp.async.commit_group;" ::: "memory");
            asm volatile("cp.async.wait_group 1;" ::: "memory");
        } else {
            asm volatile("cp.async.wait_group 0;" ::: "memory");
        }
        __syncthreads();

        const uint32_t* Kb = (const uint32_t*)(sm + SM_K_OFF + (size_t)(c & 1) * KV_BUF);

        float acc[4][4];
#pragma unroll
        for (int u = 0; u < 4; u++)
#pragma unroll
            for (int j = 0; j < 4; j++) acc[u][j] = 0.f;

#pragma unroll
        for (int kst = 0; kst < 4; kst++) {
            const int w0 = kst * 8 + fq;
            int ra = wm * 16 + fr;
            uint32_t ah[4];
            ah[0] = Qh[ra * 36 + w0];        ah[1] = Qh[(ra + 8) * 36 + w0];
            ah[2] = Qh[ra * 36 + w0 + 4];    ah[3] = Qh[(ra + 8) * 36 + w0 + 4];
#pragma unroll
            for (int u = 0; u < 4; u++) {
                int rb = wnq * 32 + u * 8 + fr;
                uint32_t bf[2] = {Kb[rb * 36 + w0], Kb[rb * 36 + w0 + 4]};
                mma_f16(acc[u], ah, bf);
            }
        }

        const int lr0 = wm * 16 + fr;
        const int gr0 = q0 + lr0, gr1 = gr0 + 8;
#pragma unroll
        for (int u = 0; u < 4; u++) {
            int col = c * 128 + wnq * 32 + u * 8 + fq * 2;
            float2 v0, v1;
            v0.x = (col     <= gr0) ? acc[u][0] * 0.125f : -INFINITY;
            v0.y = (col + 1 <= gr0) ? acc[u][1] * 0.125f : -INFINITY;
            v1.x = (col     <= gr1) ? acc[u][2] * 0.125f : -INFINITY;
            v1.y = (col + 1 <= gr1) ? acc[u][3] * 0.125f : -INFINITY;
            *reinterpret_cast<float2*>(&S[lr0 * S_STRIDE + col]) = v0;
            *reinterpret_cast<float2*>(&S[(lr0 + 8) * S_STRIDE + col]) = v1;
        }
        __syncthreads();
    }

    // ---- prefetch V chunk 0 (overlaps with softmax) ----
    {
#pragma unroll
        for (int p = 0; p < 4; p++) {
            int r2 = lr8 + p * 32;
            cp16(sKu + r2 * 144 + lseg * 16, v16 + kvbase + (size_t)r2 * 64 + lseg * 8);
        }
        asm volatile("cp.async.commit_group;" ::: "memory");
    }

    // ---- phase 2: softmax; final pass -> gmem attn (fp32, stcs) + fp16 P in place ----
    const int climit = nchunk * 128;
#pragma unroll 1
    for (int i = 0; i < 4; i++) {
        int r = wid * 4 + i;
        int gq = q0 + r;
        float* Sr = S + r * S_STRIDE;
        char*  Pr = reinterpret_cast<char*>(Sr);           // fp16 P aliases row base
        float mx = -INFINITY;
        for (int c = lane * 4; c < climit; c += 128) {
            float4 v = *reinterpret_cast<float4*>(&Sr[c]);
            mx = fmaxf(mx, fmaxf(fmaxf(v.x, v.y), fmaxf(v.z, v.w)));
        }
#pragma unroll
        for (int o = 16; o > 0; o >>= 1) mx = fmaxf(mx, __shfl_xor_sync(~0u, mx, o));
        float sum = 0.f;
        for (int c = lane * 4; c < climit; c += 128) {
            float4 v = *reinterpret_cast<float4*>(&Sr[c]);
            v.x = __expf(v.x - mx); v.y = __expf(v.y - mx);
            v.z = __expf(v.z - mx); v.w = __expf(v.w - mx);
            sum += v.x + v.y + v.z + v.w;
            *reinterpret_cast<float4*>(&Sr[c]) = v;
        }
#pragma unroll
        for (int o = 16; o > 0; o >>= 1) sum += __shfl_xor_sync(~0u, sum, o);
        float inv = 1.0f / sum;
        float* arow = attn + ((size_t)bh * Ss + gq) * Ss;
        for (int c = lane * 4; c < climit; c += 128) {
            float4 v = *reinterpret_cast<float4*>(&Sr[c]);
            __syncwarp();                                   // all loads before fp16 stores
            v.x *= inv; v.y *= inv; v.z *= inv; v.w *= inv;
            __stcs(reinterpret_cast<float4*>(&arow[c]), v);
            uint2 p = make_uint2(packh(v.x, v.y), packh(v.z, v.w));
            *reinterpret_cast<uint2*>(Pr + 2 * c) = p;      // bytes 2c < reads at 4c
        }
        // tail zeros handled by zero_tail kernel
    }
    __syncthreads();

    // ---- phase 3: ctx = P(fp16) @ V (V double-buffered) ----
    const int wm3 = wid & 1, wn3 = wid >> 1;     // 2m x 4n(16)
    float cacc[2][4];
#pragma unroll
    for (int u = 0; u < 2; u++)
#pragma unroll
        for (int j = 0; j < 4; j++) cacc[u][j] = 0.f;

    const int l16 = lane & 15;
    const int r0 = wm3 * 16 + fr;
    const char* Pbase = sm + (size_t)r0 * ROW_B;
    for (int c = 0; c < nchunk; c++) {
        if (c + 1 < nchunk) {
            uint32_t dst = sKu + ((c + 1) & 1) * KV_BUF;
#pragma unroll
            for (int p = 0; p < 4; p++) {
                int r2 = lr8 + p * 32;
                cp16(dst + r2 * 144 + lseg * 16,
                     v16 + kvbase + ((size_t)(c + 1) * 128 + r2) * 64 + lseg * 8);
            }
            asm volatile("cp.async.commit_group;" ::: "memory");
            asm volatile("cp.async.wait_group 1;" ::: "memory");
        } else {
            asm volatile("cp.async.wait_group 0;" ::: "memory");
        }
        __syncthreads();

        const uint32_t vbase = sKu + (uint32_t)(c & 1) * KV_BUF;

#pragma unroll 1
        for (int kk = 0; kk < 8; kk++) {
            const int kt0 = kk * 16;
            const int scol = c * 128 + kt0 + 2 * fq;
            const char* pp = Pbase + 2 * scol;
            uint32_t ah[4];
            ah[0] = *reinterpret_cast<const uint32_t*>(pp);
            ah[1] = *reinterpret_cast<const uint32_t*>(pp + 8 * ROW_B);
            ah[2] = *reinterpret_cast<const uint32_t*>(pp + 16);
            ah[3] = *reinterpret_cast<const uint32_t*>(pp + 8 * ROW_B + 16);
#pragma unroll
            for (int u = 0; u < 2; u++) {
                int seg = wn3 * 2 + u;
                uint32_t addr = vbase + (uint32_t)(kt0 + l16) * 144 + seg * 16;
                uint32_t bf[2];
                ldmx2t(bf[0], bf[1], addr);
                mma_f16(cacc[u], ah, bf);
            }
        }
        __syncthreads();
    }

    // ---- epilogue: ctx -> fp16, merged-head [B][S][E] ----
    {
        const int b = bh >> 4, h = bh & 15;
        const int t0 = q0 + r0;
#pragma unroll
        for (int u = 0; u < 2; u++) {
            int d = wn3 * 16 + u * 8 + fq * 2;
            size_t i0 = ((size_t)(b * Ss + t0) * Ee) + h * 64 + d;
            size_t i1 = ((size_t)(b * Ss + t0 + 8) * Ee) + h * 64 + d;
            *reinterpret_cast<uint32_t*>(c16 + i0) = packh(cacc[u][0], cacc[u][1]);
            *reinterpret_cast<uint32_t*>(c16 + i1) = packh(cacc[u][2], cacc[u][3]);
        }
    }
}

// ==================== host ====================
extern "C" void kernel_launch(void* const* d_in, const int* in_sizes, int n_in,
                              void* d_out, int out_size)
{
    const float* query = (const float*)d_in[0];
    const float* key_t = (const float*)d_in[1];
    const float* value = (const float*)d_in[2];
    const float* Wq = (const float*)d_in[4];
    const float* bq = (const float*)d_in[5];
    const float* Wk = (const float*)d_in[6];
    const float* bk = (const float*)d_in[7];
    const float* Wv = (const float*)d_in[8];
    const float* bv = (const float*)d_in[9];
    const float* Wo = (const float*)d_in[10];
    const float* bo = (const float*)d_in[11];
    float* out = (float*)d_out;

    float* attn_fb;
    __half *aq, *ak, *av, *wq, *wk, *wv, *wo, *q16, *k16, *v16, *c16;
    cudaGetSymbolAddress((void**)&attn_fb, g_attn);
    cudaGetSymbolAddress((void**)&aq, g_aq);
    cudaGetSymbolAddress((void**)&ak, g_ak);
    cudaGetSymbolAddress((void**)&av, g_av);
    cudaGetSymbolAddress((void**)&wq, g_wq);
    cudaGetSymbolAddress((void**)&wk, g_wk);
    cudaGetSymbolAddress((void**)&wv, g_wv);
    cudaGetSymbolAddress((void**)&wo, g_wo);
    cudaGetSymbolAddress((void**)&q16, g_q16);
    cudaGetSymbolAddress((void**)&k16, g_k16);
    cudaGetSymbolAddress((void**)&v16, g_v16);
    cudaGetSymbolAddress((void**)&c16, g_c16);

    cudaFuncSetAttribute(gemm_qkv, cudaFuncAttributeMaxDynamicSharedMemorySize, GEMM_SMEM);
    cudaFuncSetAttribute(gemm_o, cudaFuncAttributeMaxDynamicSharedMemorySize, GEMM_SMEM);
    cudaFuncSetAttribute(fused_attn, cudaFuncAttributeMaxDynamicSharedMemorySize, FUSED_SMEM);

    const long long needed = (long long)Bb * Ss * Ee + (long long)BH * Ss * Ss;
    float* attnp = ((long long)out_size >= needed) ? (out + (size_t)Bb * Ss * Ee) : attn_fb;

    // batched conversions (8 floats/thread)
    ConvArgs cin = { (const float4*)query, (const float4*)key_t, (const float4*)value,
                     (const float4*)query, aq, ak, av, aq };
    conv_batch<<<dim3(2048, 3), 256>>>(cin, 524288);
    ConvArgs cw = { (const float4*)Wq, (const float4*)Wk, (const float4*)Wv,
                    (const float4*)Wo, wq, wk, wv, wo };
    conv_batch<<<dim3(512, 4), 256>>>(cw, 131072);

    // batched QKV projections
    QKVArgs qa = { aq, ak, av, wq, wk, wv, bq, bk, bv, q16, k16, v16 };
    gemm_qkv<<<dim3(8, 32, 3), 256, GEMM_SMEM>>>(qa);

    // zero the masked tail region of attn at high occupancy
    zero_tail<<<dim3(Ss / 32, BH), 256>>>(attnp);

    // fused attention -> attn + ctx(fp16)
    fused_attn<<<dim3(Ss / 32, BH), 256, FUSED_SMEM>>>(q16, k16, v16, attnp, c16);

    // output projection
    gemm_o<<<dim3(8, 32), 256, GEMM_SMEM>>>(c16, wo, bo, out);
}

// round 12
// speedup vs baseline: 1.0187x; 1.0187x over previous
#include <cuda_runtime.h>
#include <cuda_fp16.h>
#include <math.h>
#include <stdint.h>

#define Bb 4
#define Ss 1024
#define Ee 1024
#define Hh 16
#define HD 64
#define BH (Bb*Hh)

// ---------------- scratch (no allocs allowed) ----------------
__device__ float g_attn[67108864];               // fallback if attn not in d_out
__device__ __half g_aq[Bb * Ss * Ee];
__device__ __half g_ak[Bb * Ss * Ee];
__device__ __half g_av[Bb * Ss * Ee];
__device__ __half g_wq[Ee * Ee];
__device__ __half g_wk[Ee * Ee];
__device__ __half g_wv[Ee * Ee];
__device__ __half g_wo[Ee * Ee];
__device__ __half g_q16[BH * Ss * HD];
__device__ __half g_k16[BH * Ss * HD];
__device__ __half g_v16[BH * Ss * HD];
__device__ __half g_c16[Bb * Ss * Ee];

// ==================== helpers ====================
static __device__ __forceinline__ uint32_t s2u(const void* p) {
    uint32_t a;
    asm("{ .reg .u64 t; cvta.to.shared.u64 t, %1; cvt.u32.u64 %0, t; }" : "=r"(a) : "l"(p));
    return a;
}

static __device__ __forceinline__ void cp16(uint32_t saddr, const void* g) {
    asm volatile("cp.async.cg.shared.global [%0], [%1], 16;" :: "r"(saddr), "l"(g) : "memory");
}

static __device__ __forceinline__ void mma_f16(float c[4], const uint32_t a[4], const uint32_t b[2]) {
    asm volatile(
        "mma.sync.aligned.m16n8k16.row.col.f32.f16.f16.f32 "
        "{%0,%1,%2,%3}, {%4,%5,%6,%7}, {%8,%9}, {%0,%1,%2,%3};"
        : "+f"(c[0]), "+f"(c[1]), "+f"(c[2]), "+f"(c[3])
        : "r"(a[0]), "r"(a[1]), "r"(a[2]), "r"(a[3]), "r"(b[0]), "r"(b[1]));
}

static __device__ __forceinline__ void ldmx2t(uint32_t& r0, uint32_t& r1, uint32_t addr) {
    asm volatile("ldmatrix.sync.aligned.m8n8.x2.trans.shared.b16 {%0,%1}, [%2];"
                 : "=r"(r0), "=r"(r1) : "r"(addr));
}

static __device__ __forceinline__ uint32_t packh(float x, float y) {
    __half2 h = __floats2half2_rn(x, y);
    return *reinterpret_cast<uint32_t*>(&h);
}

// ==================== batched convert: fp32 -> fp16 ====================
struct ConvArgs {
    const float4 *s0, *s1, *s2, *s3;
    __half *d0, *d1, *d2, *d3;
};

__global__ void __launch_bounds__(256) conv_batch(ConvArgs a, int n4)
{
    const float4* src; __half* dst;
    switch (blockIdx.y) {
        case 0:  src = a.s0; dst = a.d0; break;
        case 1:  src = a.s1; dst = a.d1; break;
        case 2:  src = a.s2; dst = a.d2; break;
        default: src = a.s3; dst = a.d3; break;
    }
    int i = blockIdx.x * 256 + threadIdx.x;
    if (i >= n4) return;
    float4 v = src[i];
    uint2 r = make_uint2(packh(v.x, v.y), packh(v.z, v.w));
    *reinterpret_cast<uint2*>(dst + 4 * (size_t)i) = r;
}

// ==================== fp16 mma GEMM body (R6 scalar-LDS version) ====================
#define ARR_B   10240
#define STAGE_B 20480
#define GEMM_SMEM (4 * STAGE_B)

template<int MODE>
static __device__ __forceinline__ void gemm_body(
    const __half* __restrict__ A, const __half* __restrict__ W,
    const float* __restrict__ bias, float* __restrict__ C, __half* __restrict__ C16)
{
    extern __shared__ __align__(128) char smem[];
    const uint32_t sb = s2u(smem);
    const int tid = threadIdx.x;
    const int lane = tid & 31, wid = tid >> 5;
    const int wm = wid & 3, wn = wid >> 2;
    const int bm = blockIdx.y << 7, bn = blockIdx.x << 7;
    const int K = 1024;

    const int c0 = tid << 1;
    const int lrow = c0 >> 2, lcc = c0 & 3;
    const __half* pA = A + (size_t)(bm + lrow) * K + lcc * 8;
    const __half* pW = W + (size_t)(bn + lrow) * K + lcc * 8;
    const uint32_t so = (uint32_t)(lrow * 80 + lcc * 16);

#define LOAD_STAGE(s, kt) do {                                          \
        uint32_t b_ = sb + (uint32_t)(s) * STAGE_B + so;                \
        const int ko_ = (kt) * 32;                                      \
        cp16(b_,              pA + ko_);                                \
        cp16(b_ + 16,         pA + ko_ + 8);                            \
        cp16(b_ + ARR_B,      pW + ko_);                                \
        cp16(b_ + ARR_B + 16, pW + ko_ + 8);                            \
        asm volatile("cp.async.commit_group;" ::: "memory");            \
    } while (0)

    float acc[2][8][4];
#pragma unroll
    for (int a = 0; a < 2; a++)
#pragma unroll
        for (int b = 0; b < 8; b++)
#pragma unroll
            for (int c = 0; c < 4; c++) acc[a][b][c] = 0.f;

    LOAD_STAGE(0, 0);
    LOAD_STAGE(1, 1);

    const int fr = lane >> 2, fq = lane & 3;

    for (int kt = 0; kt < 32; kt++) {
        const int s = kt & 3;
        if (kt <= 29) LOAD_STAGE((kt + 2) & 3, kt + 2);
        if (kt < 30)       asm volatile("cp.async.wait_group 2;" ::: "memory");
        else if (kt == 30) asm volatile("cp.async.wait_group 1;" ::: "memory");
        else               asm volatile("cp.async.wait_group 0;" ::: "memory");
        __syncthreads();

        const uint32_t* SA = (const uint32_t*)(smem + (size_t)s * STAGE_B);
        const uint32_t* SW = SA + ARR_B / 4;

#pragma unroll
        for (int ks = 0; ks < 2; ks++) {
            const int w0 = ks * 8 + fq;
            uint32_t ah[2][4];
#pragma unroll
            for (int mt = 0; mt < 2; mt++) {
                int ra = wm * 32 + mt * 16 + fr;
                ah[mt][0] = SA[ra * 20 + w0];
                ah[mt][1] = SA[(ra + 8) * 20 + w0];
                ah[mt][2] = SA[ra * 20 + w0 + 4];
                ah[mt][3] = SA[(ra + 8) * 20 + w0 + 4];
            }
            uint32_t bf[8][2];
#pragma unroll
            for (int nt = 0; nt < 8; nt++) {
                int rb = wn * 64 + nt * 8 + fr;
                bf[nt][0] = SW[rb * 20 + w0];
                bf[nt][1] = SW[rb * 20 + w0 + 4];
            }
#pragma unroll
            for (int mt = 0; mt < 2; mt++)
#pragma unroll
                for (int nt = 0; nt < 8; nt++)
                    mma_f16(acc[mt][nt], ah[mt], bf[nt]);
        }
    }

    // epilogue
    const int q2 = (lane & 3) * 2;
#pragma unroll
    for (int mt = 0; mt < 2; mt++) {
#pragma unroll
        for (int i = 0; i < 2; i++) {
            int m = bm + wm * 32 + mt * 16 + fr + i * 8;
#pragma unroll
            for (int nt = 0; nt < 8; nt++) {
                int n = bn + wn * 64 + nt * 8 + q2;
                float vx = acc[mt][nt][i * 2 + 0] + bias[n];
                float vy = acc[mt][nt][i * 2 + 1] + bias[n + 1];
                if (MODE) {
                    size_t idx = ((((size_t)(m >> 10) * Hh + (n >> 6)) * Ss
                                   + (size_t)(m & 1023)) << 6) + (n & 63);
                    *reinterpret_cast<uint32_t*>(C16 + idx) = packh(vx, vy);
                } else {
                    float2 v = make_float2(vx, vy);
                    *reinterpret_cast<float2*>(C + (size_t)m * Ee + n) = v;
                }
            }
        }
    }
#undef LOAD_STAGE
}

struct QKVArgs {
    const __half *A0, *A1, *A2;
    const __half *W0, *W1, *W2;
    const float  *b0, *b1, *b2;
    __half *O0, *O1, *O2;
};

__global__ void __launch_bounds__(256, 2) gemm_qkv(QKVArgs a)
{
    const __half *A, *W; const float* b; __half* O;
    switch (blockIdx.z) {
        case 0:  A = a.A0; W = a.W0; b = a.b0; O = a.O0; break;
        case 1:  A = a.A1; W = a.W1; b = a.b1; O = a.O1; break;
        default: A = a.A2; W = a.W2; b = a.b2; O = a.O2; break;
    }
    gemm_body<1>(A, W, b, nullptr, O);
}

__global__ void __launch_bounds__(256, 2) gemm_o(
    const __half* __restrict__ A, const __half* __restrict__ W,
    const float* __restrict__ bias, float* __restrict__ C)
{
    gemm_body<0>(A, W, bias, C, nullptr);
}

// ==================== fused attention (R10 winner, unchanged) ====================
#define S_STRIDE 1036
#define ROW_B    4144
#define SM_Q_OFF 132608
#define SM_K_OFF 137216
#define KV_BUF   18432
#define FUSED_SMEM (SM_K_OFF + 2 * KV_BUF)

__global__ void __launch_bounds__(256, 1) fused_attn(
    const __half* __restrict__ q16, const __half* __restrict__ k16,
    const __half* __restrict__ v16,
    float* __restrict__ attn, __half* __restrict__ c16)
{
    extern __shared__ __align__(16) char sm[];
    float* S = (float*)sm;
    const uint32_t* Qh = (const uint32_t*)(sm + SM_Q_OFF);
    const uint32_t sQu = s2u(sm + SM_Q_OFF);
    const uint32_t sKu = s2u(sm + SM_K_OFF);

    const int tid = threadIdx.x, lane = tid & 31, wid = tid >> 5;
    const int fr = lane >> 2, fq = lane & 3;
    const int bh = blockIdx.y;
    const int qt = (int)gridDim.x - 1 - (int)blockIdx.x;   // heavy tiles first
    const int q0 = qt << 5;
    const int nchunk = (q0 + 159) >> 7;
    const size_t kvbase = (size_t)bh * Ss * HD;
    const int lseg = tid & 7, lr8 = tid >> 3;

    // ---- stage Q (32x64) + K chunk 0 into buf0 ----
    {
        cp16(sQu + lr8 * 144 + lseg * 16, q16 + kvbase + (size_t)(q0 + lr8) * 64 + lseg * 8);
#pragma unroll
        for (int p = 0; p < 4; p++) {
            int r2 = lr8 + p * 32;
            cp16(sKu + r2 * 144 + lseg * 16, k16 + kvbase + (size_t)r2 * 64 + lseg * 8);
        }
        asm volatile("cp.async.commit_group;" ::: "memory");
    }

    // ---- phase 1: scores (K double-buffered) ----
    const int wm = wid & 1, wnq = wid >> 1;      // 2m x 4n(32)
    for (int c = 0; c < nchunk; c++) {
        if (c + 1 < nchunk) {
            uint32_t dst = sKu + ((c + 1) & 1) * KV_BUF;
#pragma unroll
            for (int p = 0; p < 4; p++) {
                int r2 = lr8 + p * 32;
                cp16(dst + r2 * 144 + lseg * 16,
                     k16 + kvbase + ((size_t)(c + 1) * 128 + r2) * 64 + lseg * 8);
            }
            asm volatile("cp.async.commit_group;" ::: "memory");
            asm volatile("cp.async.wait_group 1;" ::: "memory");
        } else {
            asm volatile("cp.async.wait_group 0;" ::: "memory");
        }
        __syncthreads();

        const uint32_t* Kb = (const uint32_t*)(sm + SM_K_OFF + (size_t)(c & 1) * KV_BUF);

        float acc[4][4];
#pragma unroll
        for (int u = 0; u < 4; u++)
#pragma unroll
            for (int j = 0; j < 4; j++) acc[u][j] = 0.f;

#pragma unroll
        for (int kst = 0; kst < 4; kst++) {
            const int w0 = kst * 8 + fq;
            int ra = wm * 16 + fr;
            uint32_t ah[4];
            ah[0] = Qh[ra * 36 + w0];        ah[1] = Qh[(ra + 8) * 36 + w0];
            ah[2] = Qh[ra * 36 + w0 + 4];    ah[3] = Qh[(ra + 8) * 36 + w0 + 4];
#pragma unroll
            for (int u = 0; u < 4; u++) {
                int rb = wnq * 32 + u * 8 + fr;
                uint32_t bf[2] = {Kb[rb * 36 + w0], Kb[rb * 36 + w0 + 4]};
                mma_f16(acc[u], ah, bf);
            }
        }

        const int lr0 = wm * 16 + fr;
        const int gr0 = q0 + lr0, gr1 = gr0 + 8;
#pragma unroll
        for (int u = 0; u < 4; u++) {
            int col = c * 128 + wnq * 32 + u * 8 + fq * 2;
            float2 v0, v1;
            v0.x = (col     <= gr0) ? acc[u][0] * 0.125f : -INFINITY;
            v0.y = (col + 1 <= gr0) ? acc[u][1] * 0.125f : -INFINITY;
            v1.x = (col     <= gr1) ? acc[u][2] * 0.125f : -INFINITY;
            v1.y = (col + 1 <= gr1) ? acc[u][3] * 0.125f : -INFINITY;
            *reinterpret_cast<float2*>(&S[lr0 * S_STRIDE + col]) = v0;
            *reinterpret_cast<float2*>(&S[(lr0 + 8) * S_STRIDE + col]) = v1;
        }
        __syncthreads();
    }

    // ---- prefetch V chunk 0 (overlaps with softmax) ----
    {
#pragma unroll
        for (int p = 0; p < 4; p++) {
            int r2 = lr8 + p * 32;
            cp16(sKu + r2 * 144 + lseg * 16, v16 + kvbase + (size_t)r2 * 64 + lseg * 8);
        }
        asm volatile("cp.async.commit_group;" ::: "memory");
    }

    // ---- phase 2: softmax; final pass -> gmem attn (fp32, stcs) + fp16 P in place ----
    const int climit = nchunk * 128;
#pragma unroll 1
    for (int i = 0; i < 4; i++) {
        int r = wid * 4 + i;
        int gq = q0 + r;
        float* Sr = S + r * S_STRIDE;
        char*  Pr = reinterpret_cast<char*>(Sr);           // fp16 P aliases row base
        float mx = -INFINITY;
        for (int c = lane * 4; c < climit; c += 128) {
            float4 v = *reinterpret_cast<float4*>(&Sr[c]);
            mx = fmaxf(mx, fmaxf(fmaxf(v.x, v.y), fmaxf(v.z, v.w)));
        }
#pragma unroll
        for (int o = 16; o > 0; o >>= 1) mx = fmaxf(mx, __shfl_xor_sync(~0u, mx, o));
        float sum = 0.f;
        for (int c = lane * 4; c < climit; c += 128) {
            float4 v = *reinterpret_cast<float4*>(&Sr[c]);
            v.x = __expf(v.x - mx); v.y = __expf(v.y - mx);
            v.z = __expf(v.z - mx); v.w = __expf(v.w - mx);
            sum += v.x + v.y + v.z + v.w;
            *reinterpret_cast<float4*>(&Sr[c]) = v;
        }
#pragma unroll
        for (int o = 16; o > 0; o >>= 1) sum += __shfl_xor_sync(~0u, sum, o);
        float inv = 1.0f / sum;
        float* arow = attn + ((size_t)bh * Ss + gq) * Ss;
        for (int c = lane * 4; c < climit; c += 128) {
            float4 v = *reinterpret_cast<float4*>(&Sr[c]);
            __syncwarp();                                   // all loads before fp16 stores
            v.x *= inv; v.y *= inv; v.z *= inv; v.w *= inv;
            __stcs(reinterpret_cast<float4*>(&arow[c]), v);
            uint2 p = make_uint2(packh(v.x, v.y), packh(v.z, v.w));
            *reinterpret_cast<uint2*>(Pr + 2 * c) = p;      // bytes 2c < reads at 4c
        }
        float4 z = make_float4(0.f, 0.f, 0.f, 0.f);
        for (int c = climit + lane * 4; c < Ss; c += 128)
            __stcs(reinterpret_cast<float4*>(&arow[c]), z);
    }
    __syncthreads();

    // ---- phase 3: ctx = P(fp16) @ V (V double-buffered) ----
    const int wm3 = wid & 1, wn3 = wid >> 1;     // 2m x 4n(16)
    float cacc[2][4];
#pragma unroll
    for (int u = 0; u < 2; u++)
#pragma unroll
        for (int j = 0; j < 4; j++) cacc[u][j] = 0.f;

    const int l16 = lane & 15;
    const int r0 = wm3 * 16 + fr;
    const char* Pbase = sm + (size_t)r0 * ROW_B;
    for (int c = 0; c < nchunk; c++) {
        if (c + 1 < nchunk) {
            uint32_t dst = sKu + ((c + 1) & 1) * KV_BUF;
#pragma unroll
            for (int p = 0; p < 4; p++) {
                int r2 = lr8 + p * 32;
                cp16(dst + r2 * 144 + lseg * 16,
                     v16 + kvbase + ((size_t)(c + 1) * 128 + r2) * 64 + lseg * 8);
            }
            asm volatile("cp.async.commit_group;" ::: "memory");
            asm volatile("cp.async.wait_group 1;" ::: "memory");
        } else {
            asm volatile("cp.async.wait_group 0;" ::: "memory");
        }
        __syncthreads();

        const uint32_t vbase = sKu + (uint32_t)(c & 1) * KV_BUF;

#pragma unroll 1
        for (int kk = 0; kk < 8; kk++) {
            const int kt0 = kk * 16;
            const int scol = c * 128 + kt0 + 2 * fq;
            const char* pp = Pbase + 2 * scol;
            uint32_t ah[4];
            ah[0] = *reinterpret_cast<const uint32_t*>(pp);
            ah[1] = *reinterpret_cast<const uint32_t*>(pp + 8 * ROW_B);
            ah[2] = *reinterpret_cast<const uint32_t*>(pp + 16);
            ah[3] = *reinterpret_cast<const uint32_t*>(pp + 8 * ROW_B + 16);
#pragma unroll
            for (int u = 0; u < 2; u++) {
                int seg = wn3 * 2 + u;
                uint32_t addr = vbase + (uint32_t)(kt0 + l16) * 144 + seg * 16;
                uint32_t bf[2];
                ldmx2t(bf[0], bf[1], addr);
                mma_f16(cacc[u], ah, bf);
            }
        }
        __syncthreads();
    }

    // ---- epilogue: ctx -> fp16, merged-head [B][S][E] ----
    {
        const int b = bh >> 4, h = bh & 15;
        const int t0 = q0 + r0;
#pragma unroll
        for (int u = 0; u < 2; u++) {
            int d = wn3 * 16 + u * 8 + fq * 2;
            size_t i0 = ((size_t)(b * Ss + t0) * Ee) + h * 64 + d;
            size_t i1 = ((size_t)(b * Ss + t0 + 8) * Ee) + h * 64 + d;
            *reinterpret_cast<uint32_t*>(c16 + i0) = packh(cacc[u][0], cacc[u][1]);
            *reinterpret_cast<uint32_t*>(c16 + i1) = packh(cacc[u][2], cacc[u][3]);
        }
    }
}

// ==================== host ====================
extern "C" void kernel_launch(void* const* d_in, const int* in_sizes, int n_in,
                              void* d_out, int out_size)
{
    const float* query = (const float*)d_in[0];
    const float* key_t = (const float*)d_in[1];
    const float* value = (const float*)d_in[2];
    const float* Wq = (const float*)d_in[4];
    const float* bq = (const float*)d_in[5];
    const float* Wk = (const float*)d_in[6];
    const float* bk = (const float*)d_in[7];
    const float* Wv = (const float*)d_in[8];
    const float* bv = (const float*)d_in[9];
    const float* Wo = (const float*)d_in[10];
    const float* bo = (const float*)d_in[11];
    float* out = (float*)d_out;

    float* attn_fb;
    __half *aq, *ak, *av, *wq, *wk, *wv, *wo, *q16, *k16, *v16, *c16;
    cudaGetSymbolAddress((void**)&attn_fb, g_attn);
    cudaGetSymbolAddress((void**)&aq, g_aq);
    cudaGetSymbolAddress((void**)&ak, g_ak);
    cudaGetSymbolAddress((void**)&av, g_av);
    cudaGetSymbolAddress((void**)&wq, g_wq);
    cudaGetSymbolAddress((void**)&wk, g_wk);
    cudaGetSymbolAddress((void**)&wv, g_wv);
    cudaGetSymbolAddress((void**)&wo, g_wo);
    cudaGetSymbolAddress((void**)&q16, g_q16);
    cudaGetSymbolAddress((void**)&k16, g_k16);
    cudaGetSymbolAddress((void**)&v16, g_v16);
    cudaGetSymbolAddress((void**)&c16, g_c16);

    cudaFuncSetAttribute(gemm_qkv, cudaFuncAttributeMaxDynamicSharedMemorySize, GEMM_SMEM);
    cudaFuncSetAttribute(gemm_o, cudaFuncAttributeMaxDynamicSharedMemorySize, GEMM_SMEM);
    cudaFuncSetAttribute(fused_attn, cudaFuncAttributeMaxDynamicSharedMemorySize, FUSED_SMEM);

    const long long needed = (long long)Bb * Ss * Ee + (long long)BH * Ss * Ss;
    float* attnp = ((long long)out_size >= needed) ? (out + (size_t)Bb * Ss * Ee) : attn_fb;

    // batched conversions
    ConvArgs cin = { (const float4*)query, (const float4*)key_t, (const float4*)value,
                     (const float4*)query, aq, ak, av, aq };
    conv_batch<<<dim3(4096, 3), 256>>>(cin, 1048576);
    ConvArgs cw = { (const float4*)Wq, (const float4*)Wk, (const float4*)Wv,
                    (const float4*)Wo, wq, wk, wv, wo };
    conv_batch<<<dim3(1024, 4), 256>>>(cw, 262144);

    // batched QKV projections (2 CTAs/SM)
    QKVArgs qa = { aq, ak, av, wq, wk, wv, bq, bk, bv, q16, k16, v16 };
    gemm_qkv<<<dim3(8, 32, 3), 256, GEMM_SMEM>>>(qa);

    // fused attention -> attn + ctx(fp16)
    fused_attn<<<dim3(Ss / 32, BH), 256, FUSED_SMEM>>>(q16, k16, v16, attnp, c16);

    // output projection (2 CTAs/SM)
    gemm_o<<<dim3(8, 32), 256, GEMM_SMEM>>>(c16, wo, bo, out);
}

// round 13
// speedup vs baseline: 1.0263x; 1.0075x over previous
#include <cuda_runtime.h>
#include <cuda_fp16.h>
#include <math.h>
#include <stdint.h>

#define Bb 4
#define Ss 1024
#define Ee 1024
#define Hh 16
#define HD 64
#define BH (Bb*Hh)

// ---------------- scratch (no allocs allowed) ----------------
__device__ float g_attn[67108864];               // fallback if attn not in d_out
__device__ __half g_aq[Bb * Ss * Ee];
__device__ __half g_ak[Bb * Ss * Ee];
__device__ __half g_av[Bb * Ss * Ee];
__device__ __half g_wq[Ee * Ee];
__device__ __half g_wk[Ee * Ee];
__device__ __half g_wv[Ee * Ee];
__device__ __half g_wo[Ee * Ee];
__device__ __half g_q16[BH * Ss * HD];
__device__ __half g_k16[BH * Ss * HD];
__device__ __half g_v16[BH * Ss * HD];
__device__ __half g_c16[Bb * Ss * Ee];

// ==================== helpers ====================
static __device__ __forceinline__ uint32_t s2u(const void* p) {
    uint32_t a;
    asm("{ .reg .u64 t; cvta.to.shared.u64 t, %1; cvt.u32.u64 %0, t; }" : "=r"(a) : "l"(p));
    return a;
}

static __device__ __forceinline__ void cp16(uint32_t saddr, const void* g) {
    asm volatile("cp.async.cg.shared.global [%0], [%1], 16;" :: "r"(saddr), "l"(g) : "memory");
}

static __device__ __forceinline__ void mma_f16(float c[4], const uint32_t a[4], const uint32_t b[2]) {
    asm volatile(
        "mma.sync.aligned.m16n8k16.row.col.f32.f16.f16.f32 "
        "{%0,%1,%2,%3}, {%4,%5,%6,%7}, {%8,%9}, {%0,%1,%2,%3};"
        : "+f"(c[0]), "+f"(c[1]), "+f"(c[2]), "+f"(c[3])
        : "r"(a[0]), "r"(a[1]), "r"(a[2]), "r"(a[3]), "r"(b[0]), "r"(b[1]));
}

static __device__ __forceinline__ void ldmx2t(uint32_t& r0, uint32_t& r1, uint32_t addr) {
    asm volatile("ldmatrix.sync.aligned.m8n8.x2.trans.shared.b16 {%0,%1}, [%2];"
                 : "=r"(r0), "=r"(r1) : "r"(addr));
}

static __device__ __forceinline__ uint32_t packh(float x, float y) {
    __half2 h = __floats2half2_rn(x, y);
    return *reinterpret_cast<uint32_t*>(&h);
}

// ==================== batched convert: fp32 -> fp16 ====================
struct ConvArgs {
    const float4 *s0, *s1, *s2, *s3;
    __half *d0, *d1, *d2, *d3;
};

__global__ void __launch_bounds__(256) conv_batch(ConvArgs a, int n4)
{
    const float4* src; __half* dst;
    switch (blockIdx.y) {
        case 0:  src = a.s0; dst = a.d0; break;
        case 1:  src = a.s1; dst = a.d1; break;
        case 2:  src = a.s2; dst = a.d2; break;
        default: src = a.s3; dst = a.d3; break;
    }
    int i = blockIdx.x * 256 + threadIdx.x;
    if (i >= n4) return;
    float4 v = src[i];
    uint2 r = make_uint2(packh(v.x, v.y), packh(v.z, v.w));
    *reinterpret_cast<uint2*>(dst + 4 * (size_t)i) = r;
}

// ==================== fp16 mma GEMM body (R6 scalar-LDS version) ====================
#define ARR_B   10240
#define STAGE_B 20480
#define GEMM_SMEM (4 * STAGE_B)

template<int MODE>
static __device__ __forceinline__ void gemm_body(
    const __half* __restrict__ A, const __half* __restrict__ W,
    const float* __restrict__ bias, float* __restrict__ C, __half* __restrict__ C16)
{
    extern __shared__ __align__(128) char smem[];
    const uint32_t sb = s2u(smem);
    const int tid = threadIdx.x;
    const int lane = tid & 31, wid = tid >> 5;
    const int wm = wid & 3, wn = wid >> 2;
    const int bm = blockIdx.y << 7, bn = blockIdx.x << 7;
    const int K = 1024;

    const int c0 = tid << 1;
    const int lrow = c0 >> 2, lcc = c0 & 3;
    const __half* pA = A + (size_t)(bm + lrow) * K + lcc * 8;
    const __half* pW = W + (size_t)(bn + lrow) * K + lcc * 8;
    const uint32_t so = (uint32_t)(lrow * 80 + lcc * 16);

#define LOAD_STAGE(s, kt) do {                                          \
        uint32_t b_ = sb + (uint32_t)(s) * STAGE_B + so;                \
        const int ko_ = (kt) * 32;                                      \
        cp16(b_,              pA + ko_);                                \
        cp16(b_ + 16,         pA + ko_ + 8);                            \
        cp16(b_ + ARR_B,      pW + ko_);                                \
        cp16(b_ + ARR_B + 16, pW + ko_ + 8);                            \
        asm volatile("cp.async.commit_group;" ::: "memory");            \
    } while (0)

    float acc[2][8][4];
#pragma unroll
    for (int a = 0; a < 2; a++)
#pragma unroll
        for (int b = 0; b < 8; b++)
#pragma unroll
            for (int c = 0; c < 4; c++) acc[a][b][c] = 0.f;

    LOAD_STAGE(0, 0);
    LOAD_STAGE(1, 1);

    const int fr = lane >> 2, fq = lane & 3;

    for (int kt = 0; kt < 32; kt++) {
        const int s = kt & 3;
        if (kt <= 29) LOAD_STAGE((kt + 2) & 3, kt + 2);
        if (kt < 30)       asm volatile("cp.async.wait_group 2;" ::: "memory");
        else if (kt == 30) asm volatile("cp.async.wait_group 1;" ::: "memory");
        else               asm volatile("cp.async.wait_group 0;" ::: "memory");
        __syncthreads();

        const uint32_t* SA = (const uint32_t*)(smem + (size_t)s * STAGE_B);
        const uint32_t* SW = SA + ARR_B / 4;

#pragma unroll
        for (int ks = 0; ks < 2; ks++) {
            const int w0 = ks * 8 + fq;
            uint32_t ah[2][4];
#pragma unroll
            for (int mt = 0; mt < 2; mt++) {
                int ra = wm * 32 + mt * 16 + fr;
                ah[mt][0] = SA[ra * 20 + w0];
                ah[mt][1] = SA[(ra + 8) * 20 + w0];
                ah[mt][2] = SA[ra * 20 + w0 + 4];
                ah[mt][3] = SA[(ra + 8) * 20 + w0 + 4];
            }
            uint32_t bf[8][2];
#pragma unroll
            for (int nt = 0; nt < 8; nt++) {
                int rb = wn * 64 + nt * 8 + fr;
                bf[nt][0] = SW[rb * 20 + w0];
                bf[nt][1] = SW[rb * 20 + w0 + 4];
            }
#pragma unroll
            for (int mt = 0; mt < 2; mt++)
#pragma unroll
                for (int nt = 0; nt < 8; nt++)
                    mma_f16(acc[mt][nt], ah[mt], bf[nt]);
        }
    }

    // epilogue
    const int q2 = (lane & 3) * 2;
#pragma unroll
    for (int mt = 0; mt < 2; mt++) {
#pragma unroll
        for (int i = 0; i < 2; i++) {
            int m = bm + wm * 32 + mt * 16 + fr + i * 8;
#pragma unroll
            for (int nt = 0; nt < 8; nt++) {
                int n = bn + wn * 64 + nt * 8 + q2;
                float vx = acc[mt][nt][i * 2 + 0] + bias[n];
                float vy = acc[mt][nt][i * 2 + 1] + bias[n + 1];
                if (MODE) {
                    size_t idx = ((((size_t)(m >> 10) * Hh + (n >> 6)) * Ss
                                   + (size_t)(m & 1023)) << 6) + (n & 63);
                    *reinterpret_cast<uint32_t*>(C16 + idx) = packh(vx, vy);
                } else {
                    float2 v = make_float2(vx, vy);
                    *reinterpret_cast<float2*>(C + (size_t)m * Ee + n) = v;
                }
            }
        }
    }
#undef LOAD_STAGE
}

struct QKVArgs {
    const __half *A0, *A1, *A2;
    const __half *W0, *W1, *W2;
    const float  *b0, *b1, *b2;
    __half *O0, *O1, *O2;
};

__global__ void __launch_bounds__(256) gemm_qkv(QKVArgs a)
{
    const __half *A, *W; const float* b; __half* O;
    switch (blockIdx.z) {
        case 0:  A = a.A0; W = a.W0; b = a.b0; O = a.O0; break;
        case 1:  A = a.A1; W = a.W1; b = a.b1; O = a.O1; break;
        default: A = a.A2; W = a.W2; b = a.b2; O = a.O2; break;
    }
    gemm_body<1>(A, W, b, nullptr, O);
}

__global__ void __launch_bounds__(256) gemm_o(
    const __half* __restrict__ A, const __half* __restrict__ W,
    const float* __restrict__ bias, float* __restrict__ C)
{
    gemm_body<0>(A, W, bias, C, nullptr);
}

// ==================== fused attention v2: 2-pass online softmax, 2 CTA/SM ====================
// Block = (bh, 32 q rows), 256 threads. Pass A: QK^T in registers -> per-row (max, 1/sum).
// Pass B: recompute QK^T, write normalized fp32 attn (stcs) + fp16 P to smem.
// Phase 3: ctx = P @ V. smem ~108KB -> 2 independent CTAs per SM.
#define PROW_B   2088            // bytes per P row (1044 halves; 522 words, conflict-free)
#define SM_Q_OFF 66816
#define SM_RED_OFF 71424         // float2 red[32][4]
#define SM_STAT_OFF 72448        // float2 stat[32]
#define SM_KV_OFF 73728
#define KV_BUF   18432
#define FUSED_SMEM (SM_KV_OFF + 2 * KV_BUF)   // 110592

__global__ void __launch_bounds__(256, 2) fused_attn(
    const __half* __restrict__ q16, const __half* __restrict__ k16,
    const __half* __restrict__ v16,
    float* __restrict__ attn, __half* __restrict__ c16)
{
    extern __shared__ __align__(16) char sm[];
    char* Psm = sm;                                        // fp16 P [32][1044]
    const uint32_t* Qh = (const uint32_t*)(sm + SM_Q_OFF);
    float2* red  = (float2*)(sm + SM_RED_OFF);
    float2* stat = (float2*)(sm + SM_STAT_OFF);
    const uint32_t sQu = s2u(sm + SM_Q_OFF);
    const uint32_t sKu = s2u(sm + SM_KV_OFF);

    const int tid = threadIdx.x, lane = tid & 31, wid = tid >> 5;
    const int fr = lane >> 2, fq = lane & 3;
    const int bh = blockIdx.y;
    const int qt = (int)gridDim.x - 1 - (int)blockIdx.x;   // heavy tiles first
    const int q0 = qt << 5;
    const int nchunk = (q0 + 159) >> 7;
    const size_t kvbase = (size_t)bh * Ss * HD;
    const int lseg = tid & 7, lr8 = tid >> 3;

#define LOAD_KV(src, chunk, buf) do {                                       \
        uint32_t dst_ = sKu + (uint32_t)(buf) * KV_BUF;                     \
        _Pragma("unroll")                                                   \
        for (int p_ = 0; p_ < 4; p_++) {                                    \
            int r2_ = lr8 + p_ * 32;                                        \
            cp16(dst_ + r2_ * 144 + lseg * 16,                              \
                 (src) + kvbase + ((size_t)(chunk) * 128 + r2_) * 64 + lseg * 8); \
        }                                                                   \
        asm volatile("cp.async.commit_group;" ::: "memory");                \
    } while (0)

    // ---- stage Q (32x64) + K chunk 0 ----
    cp16(sQu + lr8 * 144 + lseg * 16, q16 + kvbase + (size_t)(q0 + lr8) * 64 + lseg * 8);
    LOAD_KV(k16, 0, 0);

    const int wm = wid & 1, wnq = wid >> 1;      // 2m x 4n(32)
    const int lr0 = wm * 16 + fr;
    const int gr0 = q0 + lr0, gr1 = gr0 + 8;

    // per-thread scores helper (shared by pass A and B)
#define SCORES_MMA(ACC, KB) do {                                            \
        _Pragma("unroll")                                                   \
        for (int kst = 0; kst < 4; kst++) {                                 \
            const int w0_ = kst * 8 + fq;                                   \
            uint32_t ah_[4];                                                \
            ah_[0] = Qh[lr0 * 36 + w0_];      ah_[1] = Qh[(lr0 + 8) * 36 + w0_]; \
            ah_[2] = Qh[lr0 * 36 + w0_ + 4];  ah_[3] = Qh[(lr0 + 8) * 36 + w0_ + 4]; \
            _Pragma("unroll")                                               \
            for (int u_ = 0; u_ < 4; u_++) {                                \
                int rb_ = wnq * 32 + u_ * 8 + fr;                           \
                uint32_t bf_[2] = {(KB)[rb_ * 36 + w0_], (KB)[rb_ * 36 + w0_ + 4]}; \
                mma_f16((ACC)[u_], ah_, bf_);                               \
            }                                                               \
        }                                                                   \
    } while (0)

    // ---- pass A: online (m, l) ----
    float m0 = -1e30f, l0 = 0.f, m1 = -1e30f, l1 = 0.f;
    for (int c = 0; c < nchunk; c++) {
        if (c + 1 < nchunk) {
            LOAD_KV(k16, c + 1, (c + 1) & 1);
            asm volatile("cp.async.wait_group 1;" ::: "memory");
        } else {
            asm volatile("cp.async.wait_group 0;" ::: "memory");
        }
        __syncthreads();
        const uint32_t* Kb = (const uint32_t*)(sm + SM_KV_OFF + (size_t)(c & 1) * KV_BUF);

        float acc[4][4];
#pragma unroll
        for (int u = 0; u < 4; u++)
#pragma unroll
            for (int j = 0; j < 4; j++) acc[u][j] = 0.f;
        SCORES_MMA(acc, Kb);

        float vv[4][4];
        float cm0 = -1e30f, cm1 = -1e30f;
#pragma unroll
        for (int u = 0; u < 4; u++) {
            int col = c * 128 + wnq * 32 + u * 8 + fq * 2;
            vv[u][0] = (col     <= gr0) ? acc[u][0] * 0.125f : -1e30f;
            vv[u][1] = (col + 1 <= gr0) ? acc[u][1] * 0.125f : -1e30f;
            vv[u][2] = (col     <= gr1) ? acc[u][2] * 0.125f : -1e30f;
            vv[u][3] = (col + 1 <= gr1) ? acc[u][3] * 0.125f : -1e30f;
            cm0 = fmaxf(cm0, fmaxf(vv[u][0], vv[u][1]));
            cm1 = fmaxf(cm1, fmaxf(vv[u][2], vv[u][3]));
        }
        float nm0 = fmaxf(m0, cm0), nm1 = fmaxf(m1, cm1);
        float s0 = 0.f, s1 = 0.f;
#pragma unroll
        for (int u = 0; u < 4; u++) {
            s0 += __expf(vv[u][0] - nm0) + __expf(vv[u][1] - nm0);
            s1 += __expf(vv[u][2] - nm1) + __expf(vv[u][3] - nm1);
        }
        l0 = l0 * __expf(m0 - nm0) + s0;  m0 = nm0;
        l1 = l1 * __expf(m1 - nm1) + s1;  m1 = nm1;
        __syncthreads();
    }

    // ---- reduce (m,l): across fq via shfl, across wnq via smem ----
#pragma unroll
    for (int o = 1; o <= 2; o <<= 1) {
        float om0 = __shfl_xor_sync(~0u, m0, o), ol0 = __shfl_xor_sync(~0u, l0, o);
        float om1 = __shfl_xor_sync(~0u, m1, o), ol1 = __shfl_xor_sync(~0u, l1, o);
        float nm0 = fmaxf(m0, om0);
        l0 = l0 * __expf(m0 - nm0) + ol0 * __expf(om0 - nm0); m0 = nm0;
        float nm1 = fmaxf(m1, om1);
        l1 = l1 * __expf(m1 - nm1) + ol1 * __expf(om1 - nm1); m1 = nm1;
    }
    if (fq == 0) {
        red[lr0 * 4 + wnq]       = make_float2(m0, l0);
        red[(lr0 + 8) * 4 + wnq] = make_float2(m1, l1);
    }
    __syncthreads();
    if (tid < 32) {
        float2 a = red[tid * 4 + 0], b = red[tid * 4 + 1];
        float2 c2 = red[tid * 4 + 2], d = red[tid * 4 + 3];
        float mf = fmaxf(fmaxf(a.x, b.x), fmaxf(c2.x, d.x));
        float lf = a.y * __expf(a.x - mf) + b.y * __expf(b.x - mf)
                 + c2.y * __expf(c2.x - mf) + d.y * __expf(d.x - mf);
        stat[tid] = make_float2(mf, 1.0f / lf);
    }
    __syncthreads();

    // reload K chunk 0 for pass B
    LOAD_KV(k16, 0, 0);
    const float2 st0 = stat[lr0];
    const float2 st1 = stat[lr0 + 8];
    float* arow0 = attn + ((size_t)bh * Ss + gr0) * Ss;
    float* arow1 = attn + ((size_t)bh * Ss + gr1) * Ss;

    // ---- pass B: recompute scores, write attn fp32 + P fp16 smem ----
    for (int c = 0; c < nchunk; c++) {
        if (c + 1 < nchunk) LOAD_KV(k16, c + 1, (c + 1) & 1);
        else                LOAD_KV(v16, 0, nchunk & 1);     // prefetch V0
        asm volatile("cp.async.wait_group 1;" ::: "memory");
        __syncthreads();
        const uint32_t* Kb = (const uint32_t*)(sm + SM_KV_OFF + (size_t)(c & 1) * KV_BUF);

        float acc[4][4];
#pragma unroll
        for (int u = 0; u < 4; u++)
#pragma unroll
            for (int j = 0; j < 4; j++) acc[u][j] = 0.f;
        SCORES_MMA(acc, Kb);

#pragma unroll
        for (int u = 0; u < 4; u++) {
            int col = c * 128 + wnq * 32 + u * 8 + fq * 2;
            float v00 = (col     <= gr0) ? acc[u][0] * 0.125f : -1e30f;
            float v01 = (col + 1 <= gr0) ? acc[u][1] * 0.125f : -1e30f;
            float v10 = (col     <= gr1) ? acc[u][2] * 0.125f : -1e30f;
            float v11 = (col + 1 <= gr1) ? acc[u][3] * 0.125f : -1e30f;
            float p00 = __expf(v00 - st0.x) * st0.y;
            float p01 = __expf(v01 - st0.x) * st0.y;
            float p10 = __expf(v10 - st1.x) * st1.y;
            float p11 = __expf(v11 - st1.x) * st1.y;
            __stcs(reinterpret_cast<float2*>(arow0 + col), make_float2(p00, p01));
            __stcs(reinterpret_cast<float2*>(arow1 + col), make_float2(p10, p11));
            *reinterpret_cast<uint32_t*>(Psm + (size_t)lr0 * PROW_B + 2 * col) = packh(p00, p01);
            *reinterpret_cast<uint32_t*>(Psm + (size_t)(lr0 + 8) * PROW_B + 2 * col) = packh(p10, p11);
        }
        __syncthreads();
    }

    // ---- tail zeros (cols >= nchunk*128) ----
    {
        const int climit = nchunk * 128;
        const float4 z = make_float4(0.f, 0.f, 0.f, 0.f);
#pragma unroll 1
        for (int i = 0; i < 4; i++) {
            int gq = q0 + wid * 4 + i;
            float* arow = attn + ((size_t)bh * Ss + gq) * Ss;
            for (int c = climit + lane * 4; c < Ss; c += 128)
                __stcs(reinterpret_cast<float4*>(&arow[c]), z);
        }
    }

    // ---- phase 3: ctx = P(fp16) @ V (V double-buffered, parity offset nchunk) ----
    const int wm3 = wid & 1, wn3 = wid >> 1;     // 2m x 4n(16)
    float cacc[2][4];
#pragma unroll
    for (int u = 0; u < 2; u++)
#pragma unroll
        for (int j = 0; j < 4; j++) cacc[u][j] = 0.f;

    const int l16 = lane & 15;
    const int r0 = wm3 * 16 + fr;
    const char* Pbase = Psm + (size_t)r0 * PROW_B;
    for (int c = 0; c < nchunk; c++) {
        if (c + 1 < nchunk) {
            LOAD_KV(v16, c + 1, (nchunk + c + 1) & 1);
            asm volatile("cp.async.wait_group 1;" ::: "memory");
        } else {
            asm volatile("cp.async.wait_group 0;" ::: "memory");
        }
        __syncthreads();

        const uint32_t vbase = sKu + (uint32_t)((nchunk + c) & 1) * KV_BUF;

#pragma unroll 1
        for (int kk = 0; kk < 8; kk++) {
            const int kt0 = kk * 16;
            const int scol = c * 128 + kt0 + 2 * fq;
            const char* pp = Pbase + 2 * scol;
            uint32_t ah[4];
            ah[0] = *reinterpret_cast<const uint32_t*>(pp);
            ah[1] = *reinterpret_cast<const uint32_t*>(pp + 8 * PROW_B);
            ah[2] = *reinterpret_cast<const uint32_t*>(pp + 16);
            ah[3] = *reinterpret_cast<const uint32_t*>(pp + 8 * PROW_B + 16);
#pragma unroll
            for (int u = 0; u < 2; u++) {
                int seg = wn3 * 2 + u;
                uint32_t addr = vbase + (uint32_t)(kt0 + l16) * 144 + seg * 16;
                uint32_t bf[2];
                ldmx2t(bf[0], bf[1], addr);
                mma_f16(cacc[u], ah, bf);
            }
        }
        __syncthreads();
    }

    // ---- epilogue: ctx -> fp16, merged-head [B][S][E] ----
    {
        const int b = bh >> 4, h = bh & 15;
        const int t0 = q0 + r0;
#pragma unroll
        for (int u = 0; u < 2; u++) {
            int d = wn3 * 16 + u * 8 + fq * 2;
            size_t i0 = ((size_t)(b * Ss + t0) * Ee) + h * 64 + d;
            size_t i1 = ((size_t)(b * Ss + t0 + 8) * Ee) + h * 64 + d;
            *reinterpret_cast<uint32_t*>(c16 + i0) = packh(cacc[u][0], cacc[u][1]);
            *reinterpret_cast<uint32_t*>(c16 + i1) = packh(cacc[u][2], cacc[u][3]);
        }
    }
#undef LOAD_KV
#undef SCORES_MMA
}

// ==================== host ====================
extern "C" void kernel_launch(void* const* d_in, const int* in_sizes, int n_in,
                              void* d_out, int out_size)
{
    const float* query = (const float*)d_in[0];
    const float* key_t = (const float*)d_in[1];
    const float* value = (const float*)d_in[2];
    const float* Wq = (const float*)d_in[4];
    const float* bq = (const float*)d_in[5];
    const float* Wk = (const float*)d_in[6];
    const float* bk = (const float*)d_in[7];
    const float* Wv = (const float*)d_in[8];
    const float* bv = (const float*)d_in[9];
    const float* Wo = (const float*)d_in[10];
    const float* bo = (const float*)d_in[11];
    float* out = (float*)d_out;

    float* attn_fb;
    __half *aq, *ak, *av, *wq, *wk, *wv, *wo, *q16, *k16, *v16, *c16;
    cudaGetSymbolAddress((void**)&attn_fb, g_attn);
    cudaGetSymbolAddress((void**)&aq, g_aq);
    cudaGetSymbolAddress((void**)&ak, g_ak);
    cudaGetSymbolAddress((void**)&av, g_av);
    cudaGetSymbolAddress((void**)&wq, g_wq);
    cudaGetSymbolAddress((void**)&wk, g_wk);
    cudaGetSymbolAddress((void**)&wv, g_wv);
    cudaGetSymbolAddress((void**)&wo, g_wo);
    cudaGetSymbolAddress((void**)&q16, g_q16);
    cudaGetSymbolAddress((void**)&k16, g_k16);
    cudaGetSymbolAddress((void**)&v16, g_v16);
    cudaGetSymbolAddress((void**)&c16, g_c16);

    cudaFuncSetAttribute(gemm_qkv, cudaFuncAttributeMaxDynamicSharedMemorySize, GEMM_SMEM);
    cudaFuncSetAttribute(gemm_o, cudaFuncAttributeMaxDynamicSharedMemorySize, GEMM_SMEM);
    cudaFuncSetAttribute(fused_attn, cudaFuncAttributeMaxDynamicSharedMemorySize, FUSED_SMEM);

    const long long needed = (long long)Bb * Ss * Ee + (long long)BH * Ss * Ss;
    float* attnp = ((long long)out_size >= needed) ? (out + (size_t)Bb * Ss * Ee) : attn_fb;

    // batched conversions
    ConvArgs cin = { (const float4*)query, (const float4*)key_t, (const float4*)value,
                     (const float4*)query, aq, ak, av, aq };
    conv_batch<<<dim3(4096, 3), 256>>>(cin, 1048576);
    ConvArgs cw = { (const float4*)Wq, (const float4*)Wk, (const float4*)Wv,
                    (const float4*)Wo, wq, wk, wv, wo };
    conv_batch<<<dim3(1024, 4), 256>>>(cw, 262144);

    // batched QKV projections
    QKVArgs qa = { aq, ak, av, wq, wk, wv, bq, bk, bv, q16, k16, v16 };
    gemm_qkv<<<dim3(8, 32, 3), 256, GEMM_SMEM>>>(qa);

    // fused attention v2 -> attn + ctx(fp16); 2 CTAs/SM
    fused_attn<<<dim3(Ss / 32, BH), 256, FUSED_SMEM>>>(q16, k16, v16, attnp, c16);

    // output projection
    gemm_o<<<dim3(8, 32), 256, GEMM_SMEM>>>(c16, wo, bo, out);
}

// round 15
// speedup vs baseline: 1.0297x; 1.0033x over previous
#include <cuda_runtime.h>
#include <cuda_fp16.h>
#include <math.h>
#include <stdint.h>

#define Bb 4
#define Ss 1024
#define Ee 1024
#define Hh 16
#define HD 64
#define BH (Bb*Hh)

// ---------------- scratch (no allocs allowed) ----------------
__device__ float g_attn[67108864];               // fallback if attn not in d_out
__device__ __half g_aq[Bb * Ss * Ee];
__device__ __half g_ak[Bb * Ss * Ee];
__device__ __half g_av[Bb * Ss * Ee];
__device__ __half g_wq[Ee * Ee];
__device__ __half g_wk[Ee * Ee];
__device__ __half g_wv[Ee * Ee];
__device__ __half g_wo[Ee * Ee];
__device__ __half g_q16[BH * Ss * HD];
__device__ __half g_k16[BH * Ss * HD];
__device__ __half g_v16[BH * Ss * HD];
__device__ __half g_c16[Bb * Ss * Ee];

// ==================== helpers ====================
static __device__ __forceinline__ uint32_t s2u(const void* p) {
    uint32_t a;
    asm("{ .reg .u64 t; cvta.to.shared.u64 t, %1; cvt.u32.u64 %0, t; }" : "=r"(a) : "l"(p));
    return a;
}

static __device__ __forceinline__ void cp16(uint32_t saddr, const void* g) {
    asm volatile("cp.async.cg.shared.global [%0], [%1], 16;" :: "r"(saddr), "l"(g) : "memory");
}

static __device__ __forceinline__ void mma_f16(float c[4], const uint32_t a[4], const uint32_t b[2]) {
    asm volatile(
        "mma.sync.aligned.m16n8k16.row.col.f32.f16.f16.f32 "
        "{%0,%1,%2,%3}, {%4,%5,%6,%7}, {%8,%9}, {%0,%1,%2,%3};"
        : "+f"(c[0]), "+f"(c[1]), "+f"(c[2]), "+f"(c[3])
        : "r"(a[0]), "r"(a[1]), "r"(a[2]), "r"(a[3]), "r"(b[0]), "r"(b[1]));
}

static __device__ __forceinline__ void ldmx2t(uint32_t& r0, uint32_t& r1, uint32_t addr) {
    asm volatile("ldmatrix.sync.aligned.m8n8.x2.trans.shared.b16 {%0,%1}, [%2];"
                 : "=r"(r0), "=r"(r1) : "r"(addr));
}

static __device__ __forceinline__ uint32_t packh(float x, float y) {
    __half2 h = __floats2half2_rn(x, y);
    return *reinterpret_cast<uint32_t*>(&h);
}

// ==================== batched convert: fp32 -> fp16 ====================
struct ConvArgs {
    const float4 *s0, *s1, *s2, *s3;
    __half *d0, *d1, *d2, *d3;
};

__global__ void __launch_bounds__(256) conv_batch(ConvArgs a, int n4)
{
    const float4* src; __half* dst;
    switch (blockIdx.y) {
        case 0:  src = a.s0; dst = a.d0; break;
        case 1:  src = a.s1; dst = a.d1; break;
        case 2:  src = a.s2; dst = a.d2; break;
        default: src = a.s3; dst = a.d3; break;
    }
    int i = blockIdx.x * 256 + threadIdx.x;
    if (i >= n4) return;
    float4 v = src[i];
    uint2 r = make_uint2(packh(v.x, v.y), packh(v.z, v.w));
    *reinterpret_cast<uint2*>(dst + 4 * (size_t)i) = r;
}

// ==================== fp16 mma GEMM body (R6 scalar-LDS version) ====================
#define ARR_B   10240
#define STAGE_B 20480
#define GEMM_SMEM (4 * STAGE_B)

template<int MODE>
static __device__ __forceinline__ void gemm_body(
    const __half* __restrict__ A, const __half* __restrict__ W,
    const float* __restrict__ bias, float* __restrict__ C, __half* __restrict__ C16)
{
    extern __shared__ __align__(128) char smem[];
    const uint32_t sb = s2u(smem);
    const int tid = threadIdx.x;
    const int lane = tid & 31, wid = tid >> 5;
    const int wm = wid & 3, wn = wid >> 2;
    const int bm = blockIdx.y << 7, bn = blockIdx.x << 7;
    const int K = 1024;

    const int c0 = tid << 1;
    const int lrow = c0 >> 2, lcc = c0 & 3;
    const __half* pA = A + (size_t)(bm + lrow) * K + lcc * 8;
    const __half* pW = W + (size_t)(bn + lrow) * K + lcc * 8;
    const uint32_t so = (uint32_t)(lrow * 80 + lcc * 16);

#define LOAD_STAGE(s, kt) do {                                          \
        uint32_t b_ = sb + (uint32_t)(s) * STAGE_B + so;                \
        const int ko_ = (kt) * 32;                                      \
        cp16(b_,              pA + ko_);                                \
        cp16(b_ + 16,         pA + ko_ + 8);                            \
        cp16(b_ + ARR_B,      pW + ko_);                                \
        cp16(b_ + ARR_B + 16, pW + ko_ + 8);                            \
        asm volatile("cp.async.commit_group;" ::: "memory");            \
    } while (0)

    float acc[2][8][4];
#pragma unroll
    for (int a = 0; a < 2; a++)
#pragma unroll
        for (int b = 0; b < 8; b++)
#pragma unroll
            for (int c = 0; c < 4; c++) acc[a][b][c] = 0.f;

    LOAD_STAGE(0, 0);
    LOAD_STAGE(1, 1);

    const int fr = lane >> 2, fq = lane & 3;

    for (int kt = 0; kt < 32; kt++) {
        const int s = kt & 3;
        if (kt <= 29) LOAD_STAGE((kt + 2) & 3, kt + 2);
        if (kt < 30)       asm volatile("cp.async.wait_group 2;" ::: "memory");
        else if (kt == 30) asm volatile("cp.async.wait_group 1;" ::: "memory");
        else               asm volatile("cp.async.wait_group 0;" ::: "memory");
        __syncthreads();

        const uint32_t* SA = (const uint32_t*)(smem + (size_t)s * STAGE_B);
        const uint32_t* SW = SA + ARR_B / 4;

#pragma unroll
        for (int ks = 0; ks < 2; ks++) {
            const int w0 = ks * 8 + fq;
            uint32_t ah[2][4];
#pragma unroll
            for (int mt = 0; mt < 2; mt++) {
                int ra = wm * 32 + mt * 16 + fr;
                ah[mt][0] = SA[ra * 20 + w0];
                ah[mt][1] = SA[(ra + 8) * 20 + w0];
                ah[mt][2] = SA[ra * 20 + w0 + 4];
                ah[mt][3] = SA[(ra + 8) * 20 + w0 + 4];
            }
            uint32_t bf[8][2];
#pragma unroll
            for (int nt = 0; nt < 8; nt++) {
                int rb = wn * 64 + nt * 8 + fr;
                bf[nt][0] = SW[rb * 20 + w0];
                bf[nt][1] = SW[rb * 20 + w0 + 4];
            }
#pragma unroll
            for (int mt = 0; mt < 2; mt++)
#pragma unroll
                for (int nt = 0; nt < 8; nt++)
                    mma_f16(acc[mt][nt], ah[mt], bf[nt]);
        }
    }

    // epilogue
    const int q2 = (lane & 3) * 2;
#pragma unroll
    for (int mt = 0; mt < 2; mt++) {
#pragma unroll
        for (int i = 0; i < 2; i++) {
            int m = bm + wm * 32 + mt * 16 + fr + i * 8;
#pragma unroll
            for (int nt = 0; nt < 8; nt++) {
                int n = bn + wn * 64 + nt * 8 + q2;
                float vx = acc[mt][nt][i * 2 + 0] + bias[n];
                float vy = acc[mt][nt][i * 2 + 1] + bias[n + 1];
                if (MODE) {
                    size_t idx = ((((size_t)(m >> 10) * Hh + (n >> 6)) * Ss
                                   + (size_t)(m & 1023)) << 6) + (n & 63);
                    *reinterpret_cast<uint32_t*>(C16 + idx) = packh(vx, vy);
                } else {
                    float2 v = make_float2(vx, vy);
                    *reinterpret_cast<float2*>(C + (size_t)m * Ee + n) = v;
                }
            }
        }
    }
#undef LOAD_STAGE
}

struct QKVArgs {
    const __half *A0, *A1, *A2;
    const __half *W0, *W1, *W2;
    const float  *b0, *b1, *b2;
    __half *O0, *O1, *O2;
};

__global__ void __launch_bounds__(256) gemm_qkv(QKVArgs a)
{
    const __half *A, *W; const float* b; __half* O;
    switch (blockIdx.z) {
        case 0:  A = a.A0; W = a.W0; b = a.b0; O = a.O0; break;
        case 1:  A = a.A1; W = a.W1; b = a.b1; O = a.O1; break;
        default: A = a.A2; W = a.W2; b = a.b2; O = a.O2; break;
    }
    gemm_body<1>(A, W, b, nullptr, O);
}

__global__ void __launch_bounds__(256) gemm_o(
    const __half* __restrict__ A, const __half* __restrict__ W,
    const float* __restrict__ bias, float* __restrict__ C)
{
    gemm_body<0>(A, W, bias, C, nullptr);
}

// ==================== fused attention v3b: merged P@V + fixed barrier ====================
// Pass A: QK^T in registers -> per-row (max, 1/sum).
// Merged pass: per chunk, recompute scores -> write attn + P(chunk) fp16 smem -> ctx += P@V,
// then a trailing barrier so no warp's prefetch can overwrite a V tile still being read.
// smem 88KB -> 2 CTAs/SM.
#define PCH_B    264             // per-chunk P row stride (128 halves + 8B pad)
#define SM_P_OFF 0               // 32*264 = 8448
#define SM_Q_OFF 8448            // 4608
#define SM_RED_OFF 13056         // 1024
#define SM_STAT_OFF 14080        // 256
#define SM_K_OFF 14336           // 2*18432
#define SM_V_OFF 51200           // 2*18432
#define KV_BUF   18432
#define FUSED_SMEM 88064

__global__ void __launch_bounds__(256, 2) fused_attn(
    const __half* __restrict__ q16, const __half* __restrict__ k16,
    const __half* __restrict__ v16,
    float* __restrict__ attn, __half* __restrict__ c16, int wa)
{
    extern __shared__ __align__(16) char sm[];
    char* Psm = sm + SM_P_OFF;
    const uint32_t* Qh = (const uint32_t*)(sm + SM_Q_OFF);
    float2* red  = (float2*)(sm + SM_RED_OFF);
    float2* stat = (float2*)(sm + SM_STAT_OFF);
    const uint32_t sQu = s2u(sm + SM_Q_OFF);
    const uint32_t sKu = s2u(sm + SM_K_OFF);
    const uint32_t sVu = s2u(sm + SM_V_OFF);

    const int tid = threadIdx.x, lane = tid & 31, wid = tid >> 5;
    const int fr = lane >> 2, fq = lane & 3;
    const int bh = blockIdx.y;
    const int qt = (int)gridDim.x - 1 - (int)blockIdx.x;   // heavy tiles first
    const int q0 = qt << 5;
    const int nchunk = (q0 + 159) >> 7;
    const size_t kvbase = (size_t)bh * Ss * HD;
    const int lseg = tid & 7, lr8 = tid >> 3;

#define LOAD_TILE(base, src, chunk) do {                                    \
        _Pragma("unroll")                                                   \
        for (int p_ = 0; p_ < 4; p_++) {                                    \
            int r2_ = lr8 + p_ * 32;                                        \
            cp16((base) + r2_ * 144 + lseg * 16,                            \
                 (src) + kvbase + ((size_t)(chunk) * 128 + r2_) * 64 + lseg * 8); \
        }                                                                   \
    } while (0)
#define COMMIT() asm volatile("cp.async.commit_group;" ::: "memory")

    // ---- stage Q (32x64) + K chunk 0 ----
    cp16(sQu + lr8 * 144 + lseg * 16, q16 + kvbase + (size_t)(q0 + lr8) * 64 + lseg * 8);
    LOAD_TILE(sKu, k16, 0);
    COMMIT();

    const int wm = wid & 1, wnq = wid >> 1;      // 2m x 4n(32)
    const int lr0 = wm * 16 + fr;
    const int gr0 = q0 + lr0, gr1 = gr0 + 8;

#define SCORES_MMA(ACC, KB) do {                                            \
        _Pragma("unroll")                                                   \
        for (int kst = 0; kst < 4; kst++) {                                 \
            const int w0_ = kst * 8 + fq;                                   \
            uint32_t ah_[4];                                                \
            ah_[0] = Qh[lr0 * 36 + w0_];      ah_[1] = Qh[(lr0 + 8) * 36 + w0_]; \
            ah_[2] = Qh[lr0 * 36 + w0_ + 4];  ah_[3] = Qh[(lr0 + 8) * 36 + w0_ + 4]; \
            _Pragma("unroll")                                               \
            for (int u_ = 0; u_ < 4; u_++) {                                \
                int rb_ = wnq * 32 + u_ * 8 + fr;                           \
                uint32_t bf_[2] = {(KB)[rb_ * 36 + w0_], (KB)[rb_ * 36 + w0_ + 4]}; \
                mma_f16((ACC)[u_], ah_, bf_);                               \
            }                                                               \
        }                                                                   \
    } while (0)

    // ---- pass A: online (m, l), K only ----
    float m0 = -1e30f, l0 = 0.f, m1 = -1e30f, l1 = 0.f;
    for (int c = 0; c < nchunk; c++) {
        if (c + 1 < nchunk) {
            LOAD_TILE(sKu + ((c + 1) & 1) * KV_BUF, k16, c + 1);
            COMMIT();
            asm volatile("cp.async.wait_group 1;" ::: "memory");
        } else {
            asm volatile("cp.async.wait_group 0;" ::: "memory");
        }
        __syncthreads();
        const uint32_t* Kb = (const uint32_t*)(sm + SM_K_OFF + (size_t)(c & 1) * KV_BUF);

        float acc[4][4];
#pragma unroll
        for (int u = 0; u < 4; u++)
#pragma unroll
            for (int j = 0; j < 4; j++) acc[u][j] = 0.f;
        SCORES_MMA(acc, Kb);

        float vv[4][4];
        float cm0 = -1e30f, cm1 = -1e30f;
#pragma unroll
        for (int u = 0; u < 4; u++) {
            int col = c * 128 + wnq * 32 + u * 8 + fq * 2;
            vv[u][0] = (col     <= gr0) ? acc[u][0] * 0.125f : -1e30f;
            vv[u][1] = (col + 1 <= gr0) ? acc[u][1] * 0.125f : -1e30f;
            vv[u][2] = (col     <= gr1) ? acc[u][2] * 0.125f : -1e30f;
            vv[u][3] = (col + 1 <= gr1) ? acc[u][3] * 0.125f : -1e30f;
            cm0 = fmaxf(cm0, fmaxf(vv[u][0], vv[u][1]));
            cm1 = fmaxf(cm1, fmaxf(vv[u][2], vv[u][3]));
        }
        float nm0 = fmaxf(m0, cm0), nm1 = fmaxf(m1, cm1);
        float s0 = 0.f, s1 = 0.f;
#pragma unroll
        for (int u = 0; u < 4; u++) {
            s0 += __expf(vv[u][0] - nm0) + __expf(vv[u][1] - nm0);
            s1 += __expf(vv[u][2] - nm1) + __expf(vv[u][3] - nm1);
        }
        l0 = l0 * __expf(m0 - nm0) + s0;  m0 = nm0;
        l1 = l1 * __expf(m1 - nm1) + s1;  m1 = nm1;
        __syncthreads();
    }

    // ---- reduce (m,l) ----
#pragma unroll
    for (int o = 1; o <= 2; o <<= 1) {
        float om0 = __shfl_xor_sync(~0u, m0, o), ol0 = __shfl_xor_sync(~0u, l0, o);
        float om1 = __shfl_xor_sync(~0u, m1, o), ol1 = __shfl_xor_sync(~0u, l1, o);
        float nm0 = fmaxf(m0, om0);
        l0 = l0 * __expf(m0 - nm0) + ol0 * __expf(om0 - nm0); m0 = nm0;
        float nm1 = fmaxf(m1, om1);
        l1 = l1 * __expf(m1 - nm1) + ol1 * __expf(om1 - nm1); m1 = nm1;
    }
    if (fq == 0) {
        red[lr0 * 4 + wnq]       = make_float2(m0, l0);
        red[(lr0 + 8) * 4 + wnq] = make_float2(m1, l1);
    }
    __syncthreads();
    if (tid < 32) {
        float2 a = red[tid * 4 + 0], b = red[tid * 4 + 1];
        float2 c2 = red[tid * 4 + 2], d = red[tid * 4 + 3];
        float mf = fmaxf(fmaxf(a.x, b.x), fmaxf(c2.x, d.x));
        float lf = a.y * __expf(a.x - mf) + b.y * __expf(b.x - mf)
                 + c2.y * __expf(c2.x - mf) + d.y * __expf(d.x - mf);
        stat[tid] = make_float2(mf, 1.0f / lf);
    }
    __syncthreads();

    // prefetch K0 + V0
    LOAD_TILE(sKu, k16, 0);
    LOAD_TILE(sVu, v16, 0);
    COMMIT();

    const float2 st0 = stat[lr0];
    const float2 st1 = stat[lr0 + 8];
    float* arow0 = attn + ((size_t)bh * Ss + gr0) * Ss;
    float* arow1 = attn + ((size_t)bh * Ss + gr1) * Ss;

    // ctx accumulators (phase-3 mapping: 2m x 4n(16 d-cols))
    const int wm3 = wid & 1, wn3 = wid >> 1;
    const int l16 = lane & 15;
    const int r0 = wm3 * 16 + fr;
    const char* Pbase = Psm + (size_t)r0 * PCH_B;
    float cacc[2][4];
#pragma unroll
    for (int u = 0; u < 2; u++)
#pragma unroll
        for (int j = 0; j < 4; j++) cacc[u][j] = 0.f;

    // ---- merged pass: scores -> attn + P(chunk) -> ctx += P @ V ----
    for (int c = 0; c < nchunk; c++) {
        if (c + 1 < nchunk) {
            LOAD_TILE(sKu + ((c + 1) & 1) * KV_BUF, k16, c + 1);
            LOAD_TILE(sVu + ((c + 1) & 1) * KV_BUF, v16, c + 1);
            COMMIT();
            asm volatile("cp.async.wait_group 1;" ::: "memory");
        } else {
            asm volatile("cp.async.wait_group 0;" ::: "memory");
        }
        __syncthreads();     // KV_c ready; P buffer free

        const uint32_t* Kb = (const uint32_t*)(sm + SM_K_OFF + (size_t)(c & 1) * KV_BUF);

        float acc[4][4];
#pragma unroll
        for (int u = 0; u < 4; u++)
#pragma unroll
            for (int j = 0; j < 4; j++) acc[u][j] = 0.f;
        SCORES_MMA(acc, Kb);

#pragma unroll
        for (int u = 0; u < 4; u++) {
            int lcol = wnq * 32 + u * 8 + fq * 2;
            int col = c * 128 + lcol;
            float v00 = (col     <= gr0) ? acc[u][0] * 0.125f : -1e30f;
            float v01 = (col + 1 <= gr0) ? acc[u][1] * 0.125f : -1e30f;
            float v10 = (col     <= gr1) ? acc[u][2] * 0.125f : -1e30f;
            float v11 = (col + 1 <= gr1) ? acc[u][3] * 0.125f : -1e30f;
            float p00 = __expf(v00 - st0.x) * st0.y;
            float p01 = __expf(v01 - st0.x) * st0.y;
            float p10 = __expf(v10 - st1.x) * st1.y;
            float p11 = __expf(v11 - st1.x) * st1.y;
            if (wa) {
                __stcs(reinterpret_cast<float2*>(arow0 + col), make_float2(p00, p01));
                __stcs(reinterpret_cast<float2*>(arow1 + col), make_float2(p10, p11));
            }
            *reinterpret_cast<uint32_t*>(Psm + (size_t)lr0 * PCH_B + 2 * lcol) = packh(p00, p01);
            *reinterpret_cast<uint32_t*>(Psm + (size_t)(lr0 + 8) * PCH_B + 2 * lcol) = packh(p10, p11);
        }
        __syncthreads();     // P chunk complete

        const uint32_t vbase = sVu + (uint32_t)(c & 1) * KV_BUF;
#pragma unroll 1
        for (int kk = 0; kk < 8; kk++) {
            const int kt0 = kk * 16;
            const char* pp = Pbase + 2 * (kt0 + 2 * fq);
            uint32_t ah[4];
            ah[0] = *reinterpret_cast<const uint32_t*>(pp);
            ah[1] = *reinterpret_cast<const uint32_t*>(pp + 8 * PCH_B);
            ah[2] = *reinterpret_cast<const uint32_t*>(pp + 16);
            ah[3] = *reinterpret_cast<const uint32_t*>(pp + 8 * PCH_B + 16);
#pragma unroll
            for (int u = 0; u < 2; u++) {
                int seg = wn3 * 2 + u;
                uint32_t addr = vbase + (uint32_t)(kt0 + l16) * 144 + seg * 16;
                uint32_t bf[2];
                ldmx2t(bf[0], bf[1], addr);
                mma_f16(cacc[u], ah, bf);
            }
        }
        __syncthreads();     // FIX: all V/P reads done before next prefetch overwrites
    }

    // ---- tail zeros (cols >= nchunk*128) ----
    if (wa) {
        const int climit = nchunk * 128;
        const float4 z = make_float4(0.f, 0.f, 0.f, 0.f);
#pragma unroll 1
        for (int i = 0; i < 4; i++) {
            int gq = q0 + wid * 4 + i;
            float* arow = attn + ((size_t)bh * Ss + gq) * Ss;
            for (int c = climit + lane * 4; c < Ss; c += 128)
                __stcs(reinterpret_cast<float4*>(&arow[c]), z);
        }
    }

    // ---- epilogue: ctx -> fp16, merged-head [B][S][E] ----
    {
        const int b = bh >> 4, h = bh & 15;
        const int t0 = q0 + r0;
#pragma unroll
        for (int u = 0; u < 2; u++) {
            int d = wn3 * 16 + u * 8 + fq * 2;
            size_t i0 = ((size_t)(b * Ss + t0) * Ee) + h * 64 + d;
            size_t i1 = ((size_t)(b * Ss + t0 + 8) * Ee) + h * 64 + d;
            *reinterpret_cast<uint32_t*>(c16 + i0) = packh(cacc[u][0], cacc[u][1]);
            *reinterpret_cast<uint32_t*>(c16 + i1) = packh(cacc[u][2], cacc[u][3]);
        }
    }
#undef LOAD_TILE
#undef COMMIT
#undef SCORES_MMA
}

// ==================== host ====================
extern "C" void kernel_launch(void* const* d_in, const int* in_sizes, int n_in,
                              void* d_out, int out_size)
{
    const float* query = (const float*)d_in[0];
    const float* key_t = (const float*)d_in[1];
    const float* value = (const float*)d_in[2];
    const float* Wq = (const float*)d_in[4];
    const float* bq = (const float*)d_in[5];
    const float* Wk = (const float*)d_in[6];
    const float* bk = (const float*)d_in[7];
    const float* Wv = (const float*)d_in[8];
    const float* bv = (const float*)d_in[9];
    const float* Wo = (const float*)d_in[10];
    const float* bo = (const float*)d_in[11];
    float* out = (float*)d_out;

    float* attn_fb;
    __half *aq, *ak, *av, *wq, *wk, *wv, *wo, *q16, *k16, *v16, *c16;
    cudaGetSymbolAddress((void**)&attn_fb, g_attn);
    cudaGetSymbolAddress((void**)&aq, g_aq);
    cudaGetSymbolAddress((void**)&ak, g_ak);
    cudaGetSymbolAddress((void**)&av, g_av);
    cudaGetSymbolAddress((void**)&wq, g_wq);
    cudaGetSymbolAddress((void**)&wk, g_wk);
    cudaGetSymbolAddress((void**)&wv, g_wv);
    cudaGetSymbolAddress((void**)&wo, g_wo);
    cudaGetSymbolAddress((void**)&q16, g_q16);
    cudaGetSymbolAddress((void**)&k16, g_k16);
    cudaGetSymbolAddress((void**)&v16, g_v16);
    cudaGetSymbolAddress((void**)&c16, g_c16);

    cudaFuncSetAttribute(gemm_qkv, cudaFuncAttributeMaxDynamicSharedMemorySize, GEMM_SMEM);
    cudaFuncSetAttribute(gemm_o, cudaFuncAttributeMaxDynamicSharedMemorySize, GEMM_SMEM);
    cudaFuncSetAttribute(fused_attn, cudaFuncAttributeMaxDynamicSharedMemorySize, FUSED_SMEM);

    const long long needed = (long long)Bb * Ss * Ee + (long long)BH * Ss * Ss;
    const int wa = ((long long)out_size >= needed) ? 1 : 0;
    float* attnp = wa ? (out + (size_t)Bb * Ss * Ee) : attn_fb;

    // batched conversions
    ConvArgs cin = { (const float4*)query, (const float4*)key_t, (const float4*)value,
                     (const float4*)query, aq, ak, av, aq };
    conv_batch<<<dim3(4096, 3), 256>>>(cin, 1048576);
    ConvArgs cw = { (const float4*)Wq, (const float4*)Wk, (const float4*)Wv,
                    (const float4*)Wo, wq, wk, wv, wo };
    conv_batch<<<dim3(1024, 4), 256>>>(cw, 262144);

    // batched QKV projections
    QKVArgs qa = { aq, ak, av, wq, wk, wv, bq, bk, bv, q16, k16, v16 };
    gemm_qkv<<<dim3(8, 32, 3), 256, GEMM_SMEM>>>(qa);

    // fused attention v3b -> attn + ctx(fp16); 2 CTAs/SM
    fused_attn<<<dim3(Ss / 32, BH), 256, FUSED_SMEM>>>(q16, k16, v16, attnp, c16, wa);

    // output projection
    gemm_o<<<dim3(8, 32), 256, GEMM_SMEM>>>(c16, wo, bo, out);
}

// round 16
// speedup vs baseline: 1.0926x; 1.0611x over previous
#include <cuda_runtime.h>
#include <cuda_fp16.h>
#include <math.h>
#include <stdint.h>

#define Bb 4
#define Ss 1024
#define Ee 1024
#define Hh 16
#define HD 64
#define BH (Bb*Hh)

// ---------------- scratch (no allocs allowed) ----------------
__device__ float g_attn[67108864];               // fallback if attn not in d_out
__device__ __half g_aq[Bb * Ss * Ee];
__device__ __half g_ak[Bb * Ss * Ee];
__device__ __half g_av[Bb * Ss * Ee];
__device__ __half g_wq[Ee * Ee];
__device__ __half g_wk[Ee * Ee];
__device__ __half g_wv[Ee * Ee];
__device__ __half g_wo[Ee * Ee];
__device__ __half g_q16[BH * Ss * HD];
__device__ __half g_k16[BH * Ss * HD];
__device__ __half g_v16[BH * Ss * HD];
__device__ __half g_c16[Bb * Ss * Ee];

// ==================== helpers ====================
static __device__ __forceinline__ uint32_t s2u(const void* p) {
    uint32_t a;
    asm("{ .reg .u64 t; cvta.to.shared.u64 t, %1; cvt.u32.u64 %0, t; }" : "=r"(a) : "l"(p));
    return a;
}

static __device__ __forceinline__ void cp16(uint32_t saddr, const void* g) {
    asm volatile("cp.async.cg.shared.global [%0], [%1], 16;" :: "r"(saddr), "l"(g) : "memory");
}

static __device__ __forceinline__ void mma_f16(float c[4], const uint32_t a[4], const uint32_t b[2]) {
    asm volatile(
        "mma.sync.aligned.m16n8k16.row.col.f32.f16.f16.f32 "
        "{%0,%1,%2,%3}, {%4,%5,%6,%7}, {%8,%9}, {%0,%1,%2,%3};"
        : "+f"(c[0]), "+f"(c[1]), "+f"(c[2]), "+f"(c[3])
        : "r"(a[0]), "r"(a[1]), "r"(a[2]), "r"(a[3]), "r"(b[0]), "r"(b[1]));
}

static __device__ __forceinline__ void ldmx2t(uint32_t& r0, uint32_t& r1, uint32_t addr) {
    asm volatile("ldmatrix.sync.aligned.m8n8.x2.trans.shared.b16 {%0,%1}, [%2];"
                 : "=r"(r0), "=r"(r1) : "r"(addr));
}

static __device__ __forceinline__ uint32_t packh(float x, float y) {
    __half2 h = __floats2half2_rn(x, y);
    return *reinterpret_cast<uint32_t*>(&h);
}

// ==================== batched convert: fp32 -> fp16 ====================
struct ConvArgs {
    const float4 *s0, *s1, *s2, *s3;
    __half *d0, *d1, *d2, *d3;
};

__global__ void __launch_bounds__(256) conv_batch(ConvArgs a, int n4)
{
    const float4* src; __half* dst;
    switch (blockIdx.y) {
        case 0:  src = a.s0; dst = a.d0; break;
        case 1:  src = a.s1; dst = a.d1; break;
        case 2:  src = a.s2; dst = a.d2; break;
        default: src = a.s3; dst = a.d3; break;
    }
    int i = blockIdx.x * 256 + threadIdx.x;
    if (i >= n4) return;
    float4 v = src[i];
    uint2 r = make_uint2(packh(v.x, v.y), packh(v.z, v.w));
    *reinterpret_cast<uint2*>(dst + 4 * (size_t)i) = r;
}

// ==================== fp16 mma GEMM body (R6 scalar-LDS version) ====================
#define ARR_B   10240
#define STAGE_B 20480
#define GEMM_SMEM (4 * STAGE_B)

template<int MODE>
static __device__ __forceinline__ void gemm_body(
    const __half* __restrict__ A, const __half* __restrict__ W,
    const float* __restrict__ bias, float* __restrict__ C, __half* __restrict__ C16)
{
    extern __shared__ __align__(128) char smem[];
    const uint32_t sb = s2u(smem);
    const int tid = threadIdx.x;
    const int lane = tid & 31, wid = tid >> 5;
    const int wm = wid & 3, wn = wid >> 2;
    const int bm = blockIdx.y << 7, bn = blockIdx.x << 7;
    const int K = 1024;

    const int c0 = tid << 1;
    const int lrow = c0 >> 2, lcc = c0 & 3;
    const __half* pA = A + (size_t)(bm + lrow) * K + lcc * 8;
    const __half* pW = W + (size_t)(bn + lrow) * K + lcc * 8;
    const uint32_t so = (uint32_t)(lrow * 80 + lcc * 16);

#define LOAD_STAGE(s, kt) do {                                          \
        uint32_t b_ = sb + (uint32_t)(s) * STAGE_B + so;                \
        const int ko_ = (kt) * 32;                                      \
        cp16(b_,              pA + ko_);                                \
        cp16(b_ + 16,         pA + ko_ + 8);                            \
        cp16(b_ + ARR_B,      pW + ko_);                                \
        cp16(b_ + ARR_B + 16, pW + ko_ + 8);                            \
        asm volatile("cp.async.commit_group;" ::: "memory");            \
    } while (0)

    float acc[2][8][4];
#pragma unroll
    for (int a = 0; a < 2; a++)
#pragma unroll
        for (int b = 0; b < 8; b++)
#pragma unroll
            for (int c = 0; c < 4; c++) acc[a][b][c] = 0.f;

    LOAD_STAGE(0, 0);
    LOAD_STAGE(1, 1);

    const int fr = lane >> 2, fq = lane & 3;

    for (int kt = 0; kt < 32; kt++) {
        const int s = kt & 3;
        if (kt <= 29) LOAD_STAGE((kt + 2) & 3, kt + 2);
        if (kt < 30)       asm volatile("cp.async.wait_group 2;" ::: "memory");
        else if (kt == 30) asm volatile("cp.async.wait_group 1;" ::: "memory");
        else               asm volatile("cp.async.wait_group 0;" ::: "memory");
        __syncthreads();

        const uint32_t* SA = (const uint32_t*)(smem + (size_t)s * STAGE_B);
        const uint32_t* SW = SA + ARR_B / 4;

#pragma unroll
        for (int ks = 0; ks < 2; ks++) {
            const int w0 = ks * 8 + fq;
            uint32_t ah[2][4];
#pragma unroll
            for (int mt = 0; mt < 2; mt++) {
                int ra = wm * 32 + mt * 16 + fr;
                ah[mt][0] = SA[ra * 20 + w0];
                ah[mt][1] = SA[(ra + 8) * 20 + w0];
                ah[mt][2] = SA[ra * 20 + w0 + 4];
                ah[mt][3] = SA[(ra + 8) * 20 + w0 + 4];
            }
            uint32_t bf[8][2];
#pragma unroll
            for (int nt = 0; nt < 8; nt++) {
                int rb = wn * 64 + nt * 8 + fr;
                bf[nt][0] = SW[rb * 20 + w0];
                bf[nt][1] = SW[rb * 20 + w0 + 4];
            }
#pragma unroll
            for (int mt = 0; mt < 2; mt++)
#pragma unroll
                for (int nt = 0; nt < 8; nt++)
                    mma_f16(acc[mt][nt], ah[mt], bf[nt]);
        }
    }

    // epilogue
    const int q2 = (lane & 3) * 2;
#pragma unroll
    for (int mt = 0; mt < 2; mt++) {
#pragma unroll
        for (int i = 0; i < 2; i++) {
            int m = bm + wm * 32 + mt * 16 + fr + i * 8;
#pragma unroll
            for (int nt = 0; nt < 8; nt++) {
                int n = bn + wn * 64 + nt * 8 + q2;
                float vx = acc[mt][nt][i * 2 + 0] + bias[n];
                float vy = acc[mt][nt][i * 2 + 1] + bias[n + 1];
                if (MODE) {
                    size_t idx = ((((size_t)(m >> 10) * Hh + (n >> 6)) * Ss
                                   + (size_t)(m & 1023)) << 6) + (n & 63);
                    *reinterpret_cast<uint32_t*>(C16 + idx) = packh(vx, vy);
                } else {
                    float2 v = make_float2(vx, vy);
                    *reinterpret_cast<float2*>(C + (size_t)m * Ee + n) = v;
                }
            }
        }
    }
#undef LOAD_STAGE
}

struct QKVArgs {
    const __half *A0, *A1, *A2;
    const __half *W0, *W1, *W2;
    const float  *b0, *b1, *b2;
    __half *O0, *O1, *O2;
};

__global__ void __launch_bounds__(256) gemm_qkv(QKVArgs a)
{
    const __half *A, *W; const float* b; __half* O;
    switch (blockIdx.z) {
        case 0:  A = a.A0; W = a.W0; b = a.b0; O = a.O0; break;
        case 1:  A = a.A1; W = a.W1; b = a.b1; O = a.O1; break;
        default: A = a.A2; W = a.W2; b = a.b2; O = a.O2; break;
    }
    gemm_body<1>(A, W, b, nullptr, O);
}

__global__ void __launch_bounds__(256) gemm_o(
    const __half* __restrict__ A, const __half* __restrict__ W,
    const float* __restrict__ bias, float* __restrict__ C)
{
    gemm_body<0>(A, W, bias, C, nullptr);
}

// ==================== fused attention v4: 64-row q-tiles, merged P@V, 2 CTA/SM ====================
// Pass A: QK^T (4m x 2n warps) -> per-row (max, 1/sum).
// Merged pass: per 128-col chunk: recompute scores -> attn + P(chunk) -> ctx += P@V.
#define PCH_B    264
#define SM_P_OFF 0               // 64*264 = 16896
#define SM_Q_OFF 16896           // 64*144 = 9216
#define SM_RED_OFF 26112         // 64*2*8 = 1024
#define SM_STAT_OFF 27136        // 64*8 = 512
#define SM_K_OFF 27648           // 2*18432
#define SM_V_OFF 64512           // 2*18432
#define KV_BUF   18432
#define FUSED_SMEM 101376

__global__ void __launch_bounds__(256, 2) fused_attn(
    const __half* __restrict__ q16, const __half* __restrict__ k16,
    const __half* __restrict__ v16,
    float* __restrict__ attn, __half* __restrict__ c16, int wa)
{
    extern __shared__ __align__(16) char sm[];
    char* Psm = sm + SM_P_OFF;
    const uint32_t* Qh = (const uint32_t*)(sm + SM_Q_OFF);
    float2* red  = (float2*)(sm + SM_RED_OFF);
    float2* stat = (float2*)(sm + SM_STAT_OFF);
    const uint32_t sQu = s2u(sm + SM_Q_OFF);
    const uint32_t sKu = s2u(sm + SM_K_OFF);
    const uint32_t sVu = s2u(sm + SM_V_OFF);

    const int tid = threadIdx.x, lane = tid & 31, wid = tid >> 5;
    const int fr = lane >> 2, fq = lane & 3;
    const int bh = blockIdx.y;
    const int qt = (int)gridDim.x - 1 - (int)blockIdx.x;   // heavy tiles first
    const int q0 = qt << 6;
    const int nchunk = (q0 + 191) >> 7;                    // cover cols 0..q0+63
    const size_t kvbase = (size_t)bh * Ss * HD;
    const int lseg = tid & 7, lr8 = tid >> 3;              // lr8: 0..31

#define LOAD_TILE(base, src, chunk) do {                                    \
        _Pragma("unroll")                                                   \
        for (int p_ = 0; p_ < 4; p_++) {                                    \
            int r2_ = lr8 + p_ * 32;                                        \
            cp16((base) + r2_ * 144 + lseg * 16,                            \
                 (src) + kvbase + ((size_t)(chunk) * 128 + r2_) * 64 + lseg * 8); \
        }                                                                   \
    } while (0)
#define COMMIT() asm volatile("cp.async.commit_group;" ::: "memory")

    // ---- stage Q (64x64) + K chunk 0 ----
    cp16(sQu + lr8 * 144 + lseg * 16,
         q16 + kvbase + (size_t)(q0 + lr8) * 64 + lseg * 8);
    cp16(sQu + (lr8 + 32) * 144 + lseg * 16,
         q16 + kvbase + (size_t)(q0 + lr8 + 32) * 64 + lseg * 8);
    LOAD_TILE(sKu, k16, 0);
    COMMIT();

    const int wm = wid & 3, wnq = wid >> 2;      // 4m x 2n(64)
    const int lr0 = wm * 16 + fr;                // 0..63
    const int gr0 = q0 + lr0, gr1 = gr0 + 8;

    // scores for one chunk: acc[8][4] covering cols wnq*64 + u*8
#define SCORES_MMA(ACC, KB) do {                                            \
        _Pragma("unroll")                                                   \
        for (int kst = 0; kst < 4; kst++) {                                 \
            const int w0_ = kst * 8 + fq;                                   \
            uint32_t ah_[4];                                                \
            ah_[0] = Qh[lr0 * 36 + w0_];      ah_[1] = Qh[(lr0 + 8) * 36 + w0_]; \
            ah_[2] = Qh[lr0 * 36 + w0_ + 4];  ah_[3] = Qh[(lr0 + 8) * 36 + w0_ + 4]; \
            _Pragma("unroll")                                               \
            for (int u_ = 0; u_ < 8; u_++) {                                \
                int rb_ = wnq * 64 + u_ * 8 + fr;                           \
                uint32_t bf_[2] = {(KB)[rb_ * 36 + w0_], (KB)[rb_ * 36 + w0_ + 4]}; \
                mma_f16((ACC)[u_], ah_, bf_);                               \
            }                                                               \
        }                                                                   \
    } while (0)

    // ---- pass A: online (m, l) ----
    float m0 = -1e30f, l0 = 0.f, m1 = -1e30f, l1 = 0.f;
    for (int c = 0; c < nchunk; c++) {
        if (c + 1 < nchunk) {
            LOAD_TILE(sKu + ((c + 1) & 1) * KV_BUF, k16, c + 1);
            COMMIT();
            asm volatile("cp.async.wait_group 1;" ::: "memory");
        } else {
            asm volatile("cp.async.wait_group 0;" ::: "memory");
        }
        __syncthreads();
        const uint32_t* Kb = (const uint32_t*)(sm + SM_K_OFF + (size_t)(c & 1) * KV_BUF);

        float acc[8][4];
#pragma unroll
        for (int u = 0; u < 8; u++)
#pragma unroll
            for (int j = 0; j < 4; j++) acc[u][j] = 0.f;
        SCORES_MMA(acc, Kb);

        float cm0 = -1e30f, cm1 = -1e30f;
#pragma unroll
        for (int u = 0; u < 8; u++) {
            int col = c * 128 + wnq * 64 + u * 8 + fq * 2;
            acc[u][0] = (col     <= gr0) ? acc[u][0] * 0.125f : -1e30f;
            acc[u][1] = (col + 1 <= gr0) ? acc[u][1] * 0.125f : -1e30f;
            acc[u][2] = (col     <= gr1) ? acc[u][2] * 0.125f : -1e30f;
            acc[u][3] = (col + 1 <= gr1) ? acc[u][3] * 0.125f : -1e30f;
            cm0 = fmaxf(cm0, fmaxf(acc[u][0], acc[u][1]));
            cm1 = fmaxf(cm1, fmaxf(acc[u][2], acc[u][3]));
        }
        float nm0 = fmaxf(m0, cm0), nm1 = fmaxf(m1, cm1);
        float s0 = 0.f, s1 = 0.f;
#pragma unroll
        for (int u = 0; u < 8; u++) {
            s0 += __expf(acc[u][0] - nm0) + __expf(acc[u][1] - nm0);
            s1 += __expf(acc[u][2] - nm1) + __expf(acc[u][3] - nm1);
        }
        l0 = l0 * __expf(m0 - nm0) + s0;  m0 = nm0;
        l1 = l1 * __expf(m1 - nm1) + s1;  m1 = nm1;
        __syncthreads();
    }

    // ---- reduce (m,l): across fq via shfl, across wnq (2) via smem ----
#pragma unroll
    for (int o = 1; o <= 2; o <<= 1) {
        float om0 = __shfl_xor_sync(~0u, m0, o), ol0 = __shfl_xor_sync(~0u, l0, o);
        float om1 = __shfl_xor_sync(~0u, m1, o), ol1 = __shfl_xor_sync(~0u, l1, o);
        float nm0 = fmaxf(m0, om0);
        l0 = l0 * __expf(m0 - nm0) + ol0 * __expf(om0 - nm0); m0 = nm0;
        float nm1 = fmaxf(m1, om1);
        l1 = l1 * __expf(m1 - nm1) + ol1 * __expf(om1 - nm1); m1 = nm1;
    }
    if (fq == 0) {
        red[lr0 * 2 + wnq]       = make_float2(m0, l0);
        red[(lr0 + 8) * 2 + wnq] = make_float2(m1, l1);
    }
    __syncthreads();
    if (tid < 64) {
        float2 a = red[tid * 2 + 0], b = red[tid * 2 + 1];
        float mf = fmaxf(a.x, b.x);
        float lf = a.y * __expf(a.x - mf) + b.y * __expf(b.x - mf);
        stat[tid] = make_float2(mf, 1.0f / lf);
    }
    __syncthreads();

    // prefetch K0 + V0
    LOAD_TILE(sKu, k16, 0);
    LOAD_TILE(sVu, v16, 0);
    COMMIT();

    const float2 st0 = stat[lr0];
    const float2 st1 = stat[lr0 + 8];
    float* arow0 = attn + ((size_t)bh * Ss + gr0) * Ss;
    float* arow1 = attn + ((size_t)bh * Ss + gr1) * Ss;

    // ctx mapping: 4m x 2n(32 d-cols)
    const int wm3 = wid & 3, wn3 = wid >> 2;
    const int l16 = lane & 15;
    const int r0 = wm3 * 16 + fr;
    const char* Pbase = Psm + (size_t)r0 * PCH_B;
    float cacc[4][4];
#pragma unroll
    for (int u = 0; u < 4; u++)
#pragma unroll
        for (int j = 0; j < 4; j++) cacc[u][j] = 0.f;

    // ---- merged pass: scores -> attn + P(chunk) -> ctx += P @ V ----
    for (int c = 0; c < nchunk; c++) {
        if (c + 1 < nchunk) {
            LOAD_TILE(sKu + ((c + 1) & 1) * KV_BUF, k16, c + 1);
            LOAD_TILE(sVu + ((c + 1) & 1) * KV_BUF, v16, c + 1);
            COMMIT();
            asm volatile("cp.async.wait_group 1;" ::: "memory");
        } else {
            asm volatile("cp.async.wait_group 0;" ::: "memory");
        }
        __syncthreads();

        const uint32_t* Kb = (const uint32_t*)(sm + SM_K_OFF + (size_t)(c & 1) * KV_BUF);

        float acc[8][4];
#pragma unroll
        for (int u = 0; u < 8; u++)
#pragma unroll
            for (int j = 0; j < 4; j++) acc[u][j] = 0.f;
        SCORES_MMA(acc, Kb);

#pragma unroll
        for (int u = 0; u < 8; u++) {
            int lcol = wnq * 64 + u * 8 + fq * 2;
            int col = c * 128 + lcol;
            float v00 = (col     <= gr0) ? acc[u][0] * 0.125f : -1e30f;
            float v01 = (col + 1 <= gr0) ? acc[u][1] * 0.125f : -1e30f;
            float v10 = (col     <= gr1) ? acc[u][2] * 0.125f : -1e30f;
            float v11 = (col + 1 <= gr1) ? acc[u][3] * 0.125f : -1e30f;
            float p00 = __expf(v00 - st0.x) * st0.y;
            float p01 = __expf(v01 - st0.x) * st0.y;
            float p10 = __expf(v10 - st1.x) * st1.y;
            float p11 = __expf(v11 - st1.x) * st1.y;
            if (wa) {
                __stcs(reinterpret_cast<float2*>(arow0 + col), make_float2(p00, p01));
                __stcs(reinterpret_cast<float2*>(arow1 + col), make_float2(p10, p11));
            }
            *reinterpret_cast<uint32_t*>(Psm + (size_t)lr0 * PCH_B + 2 * lcol) = packh(p00, p01);
            *reinterpret_cast<uint32_t*>(Psm + (size_t)(lr0 + 8) * PCH_B + 2 * lcol) = packh(p10, p11);
        }
        __syncthreads();     // P chunk complete

        const uint32_t vbase = sVu + (uint32_t)(c & 1) * KV_BUF;
#pragma unroll 1
        for (int kk = 0; kk < 8; kk++) {
            const int kt0 = kk * 16;
            const char* pp = Pbase + 2 * (kt0 + 2 * fq);
            uint32_t ah[4];
            ah[0] = *reinterpret_cast<const uint32_t*>(pp);
            ah[1] = *reinterpret_cast<const uint32_t*>(pp + 8 * PCH_B);
            ah[2] = *reinterpret_cast<const uint32_t*>(pp + 16);
            ah[3] = *reinterpret_cast<const uint32_t*>(pp + 8 * PCH_B + 16);
#pragma unroll
            for (int u = 0; u < 4; u++) {
                uint32_t addr = vbase + (uint32_t)(kt0 + l16) * 144 + (wn3 * 4 + u) * 16;
                uint32_t bf[2];
                ldmx2t(bf[0], bf[1], addr);
                mma_f16(cacc[u], ah, bf);
            }
        }
        __syncthreads();     // all V/P reads done before next prefetch overwrites
    }

    // ---- tail zeros (cols >= nchunk*128): 8 rows per warp ----
    if (wa) {
        const int climit = nchunk * 128;
        const float4 z = make_float4(0.f, 0.f, 0.f, 0.f);
#pragma unroll 1
        for (int i = 0; i < 8; i++) {
            int gq = q0 + wid * 8 + i;
            float* arow = attn + ((size_t)bh * Ss + gq) * Ss;
            for (int c = climit + lane * 4; c < Ss; c += 128)
                __stcs(reinterpret_cast<float4*>(&arow[c]), z);
        }
    }

    // ---- epilogue: ctx -> fp16, merged-head [B][S][E] ----
    {
        const int b = bh >> 4, h = bh & 15;
        const int t0 = q0 + r0;
#pragma unroll
        for (int u = 0; u < 4; u++) {
            int d = wn3 * 32 + u * 8 + fq * 2;
            size_t i0 = ((size_t)(b * Ss + t0) * Ee) + h * 64 + d;
            size_t i1 = ((size_t)(b * Ss + t0 + 8) * Ee) + h * 64 + d;
            *reinterpret_cast<uint32_t*>(c16 + i0) = packh(cacc[u][0], cacc[u][1]);
            *reinterpret_cast<uint32_t*>(c16 + i1) = packh(cacc[u][2], cacc[u][3]);
        }
    }
#undef LOAD_TILE
#undef COMMIT
#undef SCORES_MMA
}

// ==================== host ====================
extern "C" void kernel_launch(void* const* d_in, const int* in_sizes, int n_in,
                              void* d_out, int out_size)
{
    const float* query = (const float*)d_in[0];
    const float* key_t = (const float*)d_in[1];
    const float* value = (const float*)d_in[2];
    const float* Wq = (const float*)d_in[4];
    const float* bq = (const float*)d_in[5];
    const float* Wk = (const float*)d_in[6];
    const float* bk = (const float*)d_in[7];
    const float* Wv = (const float*)d_in[8];
    const float* bv = (const float*)d_in[9];
    const float* Wo = (const float*)d_in[10];
    const float* bo = (const float*)d_in[11];
    float* out = (float*)d_out;

    float* attn_fb;
    __half *aq, *ak, *av, *wq, *wk, *wv, *wo, *q16, *k16, *v16, *c16;
    cudaGetSymbolAddress((void**)&attn_fb, g_attn);
    cudaGetSymbolAddress((void**)&aq, g_aq);
    cudaGetSymbolAddress((void**)&ak, g_ak);
    cudaGetSymbolAddress((void**)&av, g_av);
    cudaGetSymbolAddress((void**)&wq, g_wq);
    cudaGetSymbolAddress((void**)&wk, g_wk);
    cudaGetSymbolAddress((void**)&wv, g_wv);
    cudaGetSymbolAddress((void**)&wo, g_wo);
    cudaGetSymbolAddress((void**)&q16, g_q16);
    cudaGetSymbolAddress((void**)&k16, g_k16);
    cudaGetSymbolAddress((void**)&v16, g_v16);
    cudaGetSymbolAddress((void**)&c16, g_c16);

    cudaFuncSetAttribute(gemm_qkv, cudaFuncAttributeMaxDynamicSharedMemorySize, GEMM_SMEM);
    cudaFuncSetAttribute(gemm_o, cudaFuncAttributeMaxDynamicSharedMemorySize, GEMM_SMEM);
    cudaFuncSetAttribute(fused_attn, cudaFuncAttributeMaxDynamicSharedMemorySize, FUSED_SMEM);

    const long long needed = (long long)Bb * Ss * Ee + (long long)BH * Ss * Ss;
    const int wa = ((long long)out_size >= needed) ? 1 : 0;
    float* attnp = wa ? (out + (size_t)Bb * Ss * Ee) : attn_fb;

    // batched conversions
    ConvArgs cin = { (const float4*)query, (const float4*)key_t, (const float4*)value,
                     (const float4*)query, aq, ak, av, aq };
    conv_batch<<<dim3(4096, 3), 256>>>(cin, 1048576);
    ConvArgs cw = { (const float4*)Wq, (const float4*)Wk, (const float4*)Wv,
                    (const float4*)Wo, wq, wk, wv, wo };
    conv_batch<<<dim3(1024, 4), 256>>>(cw, 262144);

    // batched QKV projections
    QKVArgs qa = { aq, ak, av, wq, wk, wv, bq, bk, bv, q16, k16, v16 };
    gemm_qkv<<<dim3(8, 32, 3), 256, GEMM_SMEM>>>(qa);

    // fused attention v4 -> attn + ctx(fp16); 64-row q-tiles, 2 CTAs/SM
    fused_attn<<<dim3(Ss / 64, BH), 256, FUSED_SMEM>>>(q16, k16, v16, attnp, c16, wa);

    // output projection
    gemm_o<<<dim3(8, 32), 256, GEMM_SMEM>>>(c16, wo, bo, out);
}